// round 13
// baseline (speedup 1.0000x reference)
#include <cuda_runtime.h>
#include <cuda_fp16.h>
#include <math.h>

#define NLEV 16
#define RESO 2048
#define PRIME_Y 2654435761u
#define FSCALE 4096.0f
#define INV_FSCALE (1.0f / 4096.0f)

#define A_STRIDE_H 40
#define W_STRIDE_H 40
#define CAP (1 << 20)

struct Levels {
    float    scale[NLEV];
    unsigned res[NLEV];
    unsigned size[NLEV];
    unsigned offset[NLEV];
    unsigned hashed[NLEV];
};

typedef unsigned long long u64;
typedef unsigned int u32;

// Sort scratch (static device memory: allocation-free, graph-safe).
__device__ u32    g_hist[65536];
__device__ u32    g_binoff[65536];
__device__ int    g_perm[CAP];
__device__ float2 g_sxy[CAP];

__device__ __forceinline__ u64 pk2(float lo, float hi) {
    u64 r; asm("mov.b64 %0,{%1,%2};" : "=l"(r) : "f"(lo), "f"(hi)); return r;
}
__device__ __forceinline__ float2 upk2(u64 a) {
    float2 f; asm("mov.b64 {%0,%1},%2;" : "=f"(f.x), "=f"(f.y) : "l"(a)); return f;
}
__device__ __forceinline__ u64 ffma2(u64 a, u64 b, u64 c) {
    u64 d; asm("fma.rn.f32x2 %0,%1,%2,%3;" : "=l"(d) : "l"(a), "l"(b), "l"(c)); return d;
}
__device__ __forceinline__ u64 mul2(u64 a, u64 b) {
    u64 d; asm("mul.rn.f32x2 %0,%1,%2;" : "=l"(d) : "l"(a), "l"(b)); return d;
}
__device__ __forceinline__ u32 cvt_h2(u64 pair) {
    float2 f = upk2(pair);
    __half2 hv = __floats2half2_rn(f.x, f.y);
    return *reinterpret_cast<u32*>(&hv);
}

__device__ __forceinline__ float decode_bound(const unsigned* p, int elems) {
    if (!p || elems <= 0) return 1.0f;
    unsigned a = p[0];
    float ff = __uint_as_float(a);
    if (isfinite(ff) && fabsf(ff) > 1e-6f && fabsf(ff) < 1e9f) return ff;
    int ai = (int)a;
    if (ai != 0 && ai > -1000000000 && ai < 1000000000) return (float)ai;
    if (elems >= 2) {
        double d = __hiloint2double((int)p[1], (int)a);
        if (isfinite(d) && fabs(d) > 1e-6 && fabs(d) < 1e9) return (float)d;
    }
    return 1.0f;
}

// Bin key: 256x256 spatial bins aligned with the (x+1)/2 grid mapping.
// Monotone in the true mapping for any bound, so locality is preserved.
__device__ __forceinline__ u32 point_key(float2 p) {
    float kx = fminf(fmaxf((p.x + 1.0f) * 0.5f, 0.0f), 1.0f);
    float ky = fminf(fmaxf((p.y + 1.0f) * 0.5f, 0.0f), 1.0f);
    u32 qx = (u32)(kx * 255.0f);
    u32 qy = (u32)(ky * 255.0f);
    return (qy << 8) | qx;
}

__global__ void zero_hist() {
    int i = blockIdx.x * blockDim.x + threadIdx.x;
    if (i < 65536) g_hist[i] = 0u;
}

__global__ void build_hist(const float2* __restrict__ xy, int N) {
    int i = blockIdx.x * blockDim.x + threadIdx.x;
    if (i < N) atomicAdd(&g_hist[point_key(xy[i])], 1u);
}

__global__ void scan_hist() {
    __shared__ u32 part[1024];
    int t = threadIdx.x;
    u32 s = 0;
    #pragma unroll 4
    for (int i = 0; i < 64; i++) s += g_hist[t * 64 + i];
    part[t] = s;
    __syncthreads();
    for (int d = 1; d < 1024; d <<= 1) {
        u32 v = 0;
        if (t >= d) v = part[t - d];
        __syncthreads();
        if (t >= d) part[t] += v;
        __syncthreads();
    }
    u32 run = (t == 0) ? 0u : part[t - 1];
    for (int i = 0; i < 64; i++) {
        u32 c = g_hist[t * 64 + i];
        g_binoff[t * 64 + i] = run;
        run += c;
    }
}

__global__ void scatter_pts(const float2* __restrict__ xy, int N) {
    int i = blockIdx.x * blockDim.x + threadIdx.x;
    if (i < N) {
        float2 p = xy[i];
        u32 pos = atomicAdd(&g_binoff[point_key(p)], 1u);
        g_perm[pos] = i;
        g_sxy[pos] = p;
    }
}

__global__ __launch_bounds__(128, 4)
void plane_kernel(const float2* __restrict__ pts,
                  const int*    __restrict__ perm,
                  const float2* __restrict__ table,
                  const float*  __restrict__ w0g,
                  const float*  __restrict__ w1g,
                  const unsigned* __restrict__ bound_raw,
                  int bound_elems,
                  float* __restrict__ out,
                  int N, Levels L)
{
    __shared__ __align__(16) __half sA[4][128 * A_STRIDE_H];
    __shared__ __align__(16) __half sW0h[64 * W_STRIDE_H];
    __shared__ __align__(16) __half sW1h[8 * 64];

    const int tid = threadIdx.x;
    const int wid = tid >> 5;
    const int lid = tid & 31;
    const int g   = lid >> 2;
    const int tig = lid & 3;

    for (int i = tid; i < 64 * 32; i += 128) {
        int j = i >> 5, k = i & 31;
        sW0h[j * W_STRIDE_H + k] = __float2half(w0g[i]);
    }
    for (int i = tid; i < 8 * 64; i += 128) sW1h[i] = __float2half(w1g[i]);
    __syncthreads();

    int slot = blockIdx.x * 128 + tid;
    int nc = (slot < N) ? slot : (N - 1);

    // Original point index of this thread's slot (for the permuted output write).
    int myTarget = slot;
    if (perm) myTarget = perm[nc];

    float bound = decode_bound(bound_raw, bound_elems);

    float2 p = pts[nc];
    float inv2b = 0.5f / bound;
    float nxv = (p.x + bound) * inv2b;
    float nyv = (p.y + bound) * inv2b;
    float cxf = fminf(fmaxf(nxv * (float)RESO - 0.5f, 0.0f), (float)(RESO - 1));
    float cyf = fminf(fmaxf(nyv * (float)RESO - 0.5f, 0.0f), (float)(RESO - 1));
    float cx0 = floorf(cxf), cy0 = floorf(cyf);
    float cx1 = fminf(cx0 + 1.0f, (float)(RESO - 1));
    float cy1 = fminf(cy0 + 1.0f, (float)(RESO - 1));
    float u = cxf - cx0, v = cyf - cy0;

    float gx0 = (cx0 + 0.5f) * (1.0f / (float)RESO);
    float gx1 = (cx1 + 0.5f) * (1.0f / (float)RESO);
    float gyA = (cy0 + 0.5f) * (1.0f / (float)RESO);
    float gyB = (cy1 + 0.5f) * (1.0f / (float)RESO);

    __half* myA = sA[wid];

    // Encode in 4-level groups, staging each group's packed fp16 features.
    #pragma unroll
    for (int lg = 0; lg < 4; lg++) {
        u32 Pa[4], Pb[4], Pc[4], Pd[4];
        #pragma unroll
        for (int li = 0; li < 4; li++) {
            const int l = lg * 4 + li;
            float    scale  = L.scale[l];
            unsigned res    = L.res[l];
            unsigned size   = L.size[l];
            unsigned off    = L.offset[l];
            bool     hashed = (L.hashed[l] != 0);

            float pxa = fmaf(gx0, scale, 0.5f);
            float pxb = fmaf(gx1, scale, 0.5f);
            float pya = fmaf(gyA, scale, 0.5f);
            float pyb = fmaf(gyB, scale, 0.5f);
            float fxa = floorf(pxa), fxb = floorf(pxb);
            float fya = floorf(pya), fyb = floorf(pyb);
            float ua1 = pxa - fxa, ua0 = 1.0f - ua1;
            float ub1 = pxb - fxb, ub0 = 1.0f - ub1;
            float va1 = (pya - fya) * FSCALE, va0 = FSCALE - va1;
            float vb1 = (pyb - fyb) * FSCALE, vb0 = FSCALE - vb1;
            unsigned ix = (unsigned)fxa, iy = (unsigned)fya;
            bool bdx = fxb > fxa;
            bool bdy = fyb > fya;

            unsigned i00, i01, i02, i10, i11, i12, i20, i21, i22;
            if (hashed) {
                unsigned m = size - 1u;
                unsigned hy0 = iy * PRIME_Y, hy1 = hy0 + PRIME_Y, hy2 = hy1 + PRIME_Y;
                i00 = (ix ^ hy0) & m; i01 = ((ix + 1u) ^ hy0) & m; i02 = ((ix + 2u) ^ hy0) & m;
                i10 = (ix ^ hy1) & m; i11 = ((ix + 1u) ^ hy1) & m; i12 = ((ix + 2u) ^ hy1) & m;
                i20 = (ix ^ hy2) & m; i21 = ((ix + 1u) ^ hy2) & m; i22 = ((ix + 2u) ^ hy2) & m;
            } else {
                unsigned hy0 = iy * res, hy1 = hy0 + res, hy2 = hy1 + res;
                i00 = ix + hy0;      if (i00 >= size) i00 -= size;
                i01 = ix + 1u + hy0; if (i01 >= size) i01 -= size;
                i02 = ix + 2u + hy0; if (i02 >= size) i02 -= size;
                i10 = ix + hy1;      if (i10 >= size) i10 -= size;
                i11 = ix + 1u + hy1; if (i11 >= size) i11 -= size;
                i12 = ix + 2u + hy1; if (i12 >= size) i12 -= size;
                i20 = ix + hy2;      if (i20 >= size) i20 -= size;
                i21 = ix + 1u + hy2; if (i21 >= size) i21 -= size;
                i22 = ix + 2u + hy2; if (i22 >= size) i22 -= size;
            }

            const u64* tb = (const u64*)(table + off);
            u64 T00 = __ldg(tb + i00);
            u64 T01 = __ldg(tb + i01);
            u64 T10 = __ldg(tb + i10);
            u64 T11 = __ldg(tb + i11);
            u64 T02 = 0ull, T12 = 0ull, T20 = 0ull, T21 = 0ull, T22 = 0ull;
            if (bdx) { T02 = __ldg(tb + i02); T12 = __ldg(tb + i12); }
            if (bdy) { T20 = __ldg(tb + i20); T21 = __ldg(tb + i21); }
            if (bdx && bdy) { T22 = __ldg(tb + i22); }

            u64 ua0p = pk2(ua0, ua0), ua1p = pk2(ua1, ua1);
            u64 ub0p = pk2(ub0, ub0), ub1p = pk2(ub1, ub1);
            u64 va0p = pk2(va0, va0), va1p = pk2(va1, va1);
            u64 vb0p = pk2(vb0, vb0), vb1p = pk2(vb1, vb1);

            u64 S00 = ffma2(ua1p, T01, mul2(ua0p, T00));
            u64 S01 = ffma2(ua1p, T11, mul2(ua0p, T10));
            u64 S02 = ffma2(ua1p, T21, mul2(ua0p, T20));
            u64 X0r0 = bdx ? T01 : T00, X1r0 = bdx ? T02 : T01;
            u64 X0r1 = bdx ? T11 : T10, X1r1 = bdx ? T12 : T11;
            u64 X0r2 = bdx ? T21 : T20, X1r2 = bdx ? T22 : T21;
            u64 S10 = ffma2(ub1p, X1r0, mul2(ub0p, X0r0));
            u64 S11 = ffma2(ub1p, X1r1, mul2(ub0p, X0r1));
            u64 S12 = ffma2(ub1p, X1r2, mul2(ub0p, X0r2));

            Pa[li] = cvt_h2(ffma2(va1p, S01, mul2(va0p, S00)));
            Pb[li] = cvt_h2(ffma2(va1p, S11, mul2(va0p, S10)));
            u64 Y0a = bdy ? S01 : S00, Y1a = bdy ? S02 : S01;
            u64 Y0b = bdy ? S11 : S10, Y1b = bdy ? S12 : S11;
            Pc[li] = cvt_h2(ffma2(vb1p, Y1a, mul2(vb0p, Y0a)));
            Pd[li] = cvt_h2(ffma2(vb1p, Y1b, mul2(vb0p, Y0b)));
        }
        *(uint4*)(myA + (0 * 32 + lid) * A_STRIDE_H + lg * 8) = make_uint4(Pa[0], Pa[1], Pa[2], Pa[3]);
        *(uint4*)(myA + (1 * 32 + lid) * A_STRIDE_H + lg * 8) = make_uint4(Pb[0], Pb[1], Pb[2], Pb[3]);
        *(uint4*)(myA + (2 * 32 + lid) * A_STRIDE_H + lg * 8) = make_uint4(Pc[0], Pc[1], Pc[2], Pc[3]);
        *(uint4*)(myA + (3 * 32 + lid) * A_STRIDE_H + lg * 8) = make_uint4(Pd[0], Pd[1], Pd[2], Pd[3]);
    }
    __syncwarp();

    u32 Bf[2][8][2];
    #pragma unroll
    for (int kc = 0; kc < 2; kc++) {
        #pragma unroll
        for (int nt = 0; nt < 8; nt++) {
            const u32* wrow = (const u32*)&sW0h[(nt * 8 + g) * W_STRIDE_H + kc * 16];
            Bf[kc][nt][0] = wrow[tig];
            Bf[kc][nt][1] = wrow[tig + 4];
        }
    }
    u32 Bf2[8];
    #pragma unroll
    for (int nt = 0; nt < 8; nt++)
        Bf2[nt] = *(const u32*)&sW1h[g * 64 + nt * 8 + tig * 2];

    float cw[4];
    cw[0] = (1.0f - u) * (1.0f - v) * INV_FSCALE;
    cw[1] = u * (1.0f - v) * INV_FSCALE;
    cw[2] = (1.0f - u) * v * INV_FSCALE;
    cw[3] = u * v * INV_FSCALE;

    const int sbase = blockIdx.x * 128 + wid * 32;

    #pragma unroll
    for (int mtp = 0; mtp < 2; mtp++) {
        float hb[8][4];
        #pragma unroll
        for (int b = 0; b < 8; b++)
            #pragma unroll
            for (int c = 0; c < 4; c++) hb[b][c] = 0.0f;

        #pragma unroll
        for (int c = 0; c < 4; c++) {
            float wlo = __shfl_sync(0xffffffffu, cw[c], mtp * 16 + g);
            float whi = __shfl_sync(0xffffffffu, cw[c], mtp * 16 + g + 8);

            u32 afr[2][4];
            #pragma unroll
            for (int kc = 0; kc < 2; kc++) {
                const __half* ar =
                    myA + (c * 32 + mtp * 16 + g) * A_STRIDE_H + kc * 16 + tig * 2;
                afr[kc][0] = *(const u32*)(ar);
                afr[kc][1] = *(const u32*)(ar + 8 * A_STRIDE_H);
                afr[kc][2] = *(const u32*)(ar + 8);
                afr[kc][3] = *(const u32*)(ar + 8 * A_STRIDE_H + 8);
            }
            #pragma unroll
            for (int nt = 0; nt < 8; nt++) {
                float d0 = 0.0f, d1 = 0.0f, d2 = 0.0f, d3 = 0.0f;
                asm volatile("mma.sync.aligned.m16n8k16.row.col.f32.f16.f16.f32 "
                    "{%0,%1,%2,%3},{%4,%5,%6,%7},{%8,%9},{%0,%1,%2,%3};"
                    : "+f"(d0), "+f"(d1), "+f"(d2), "+f"(d3)
                    : "r"(afr[0][0]), "r"(afr[0][1]), "r"(afr[0][2]), "r"(afr[0][3]),
                      "r"(Bf[0][nt][0]), "r"(Bf[0][nt][1]));
                asm volatile("mma.sync.aligned.m16n8k16.row.col.f32.f16.f16.f32 "
                    "{%0,%1,%2,%3},{%4,%5,%6,%7},{%8,%9},{%0,%1,%2,%3};"
                    : "+f"(d0), "+f"(d1), "+f"(d2), "+f"(d3)
                    : "r"(afr[1][0]), "r"(afr[1][1]), "r"(afr[1][2]), "r"(afr[1][3]),
                      "r"(Bf[1][nt][0]), "r"(Bf[1][nt][1]));
                hb[nt][0] = fmaf(fmaxf(d0, 0.0f), wlo, hb[nt][0]);
                hb[nt][1] = fmaf(fmaxf(d1, 0.0f), wlo, hb[nt][1]);
                hb[nt][2] = fmaf(fmaxf(d2, 0.0f), whi, hb[nt][2]);
                hb[nt][3] = fmaf(fmaxf(d3, 0.0f), whi, hb[nt][3]);
            }
        }

        // Layer 2 as MMA with split-h (hi + lo fp16) to remove the hidden-
        // vector quantization error (keeps total rel_err ~3e-4).
        float o0 = 0.0f, o1 = 0.0f, o2 = 0.0f, o3 = 0.0f;
        #pragma unroll
        for (int nt = 0; nt < 8; nt++) {
            __half2 h01 = __floats2half2_rn(hb[nt][0], hb[nt][1]);
            __half2 h23 = __floats2half2_rn(hb[nt][2], hb[nt][3]);
            float2 f01 = __half22float2(h01);
            float2 f23 = __half22float2(h23);
            __half2 l01 = __floats2half2_rn(hb[nt][0] - f01.x, hb[nt][1] - f01.y);
            __half2 l23 = __floats2half2_rn(hb[nt][2] - f23.x, hb[nt][3] - f23.y);
            u32 a0 = *reinterpret_cast<u32*>(&h01);
            u32 a1 = *reinterpret_cast<u32*>(&h23);
            u32 a0l = *reinterpret_cast<u32*>(&l01);
            u32 a1l = *reinterpret_cast<u32*>(&l23);
            asm volatile("mma.sync.aligned.m16n8k8.row.col.f32.f16.f16.f32 "
                "{%0,%1,%2,%3},{%4,%5},{%6},{%0,%1,%2,%3};"
                : "+f"(o0), "+f"(o1), "+f"(o2), "+f"(o3)
                : "r"(a0), "r"(a1), "r"(Bf2[nt]));
            asm volatile("mma.sync.aligned.m16n8k8.row.col.f32.f16.f16.f32 "
                "{%0,%1,%2,%3},{%4,%5},{%6},{%0,%1,%2,%3};"
                : "+f"(o0), "+f"(o1), "+f"(o2), "+f"(o3)
                : "r"(a0l), "r"(a1l), "r"(Bf2[nt]));
        }

        int s0 = sbase + mtp * 16 + g;
        int s1 = s0 + 8;
        int t0 = __shfl_sync(0xffffffffu, myTarget, mtp * 16 + g);
        int t1 = __shfl_sync(0xffffffffu, myTarget, mtp * 16 + g + 8);
        if (!perm) { t0 = s0; t1 = s1; }
        if (s0 < N)
            *(float2*)(out + (size_t)t0 * 8 + 2 * tig) = make_float2(o0, o1);
        if (s1 < N)
            *(float2*)(out + (size_t)t1 * 8 + 2 * tig) = make_float2(o2, o3);
    }
}

extern "C" void kernel_launch(void* const* d_in, const int* in_sizes, int n_in,
                              void* d_out, int out_size)
{
    const float2* xy    = (const float2*)d_in[0];
    const float2* table = (const float2*)d_in[1];
    const float*  w0    = (const float*)d_in[2];
    const float*  w1    = (const float*)d_in[3];
    const unsigned* bound = (n_in > 4) ? (const unsigned*)d_in[4] : nullptr;
    int bound_elems = (n_in > 4) ? in_sizes[4] : 0;

    int N = in_sizes[0] / 2;

    bool sorted = (N <= CAP);
    if (sorted) {
        zero_hist<<<64, 1024>>>();
        build_hist<<<(N + 255) / 256, 256>>>(xy, N);
        scan_hist<<<1, 1024>>>();
        scatter_pts<<<(N + 255) / 256, 256>>>(xy, N);
    }

    void *sxy_ptr = nullptr, *perm_ptr = nullptr;
    cudaGetSymbolAddress(&sxy_ptr, g_sxy);
    cudaGetSymbolAddress(&perm_ptr, g_perm);

    // Level constants — same double-precision libm sequence as the numpy
    // reference so ceil() boundaries match exactly.
    Levels L;
    double b = exp2(log2(2048.0 / 16.0) / 15.0);
    unsigned off = 0;
    for (int l = 0; l < NLEV; l++) {
        double s = 16.0 * pow(b, (double)l) - 1.0;
        int r = (int)ceil(s) + 1;
        unsigned long long pp = (unsigned long long)r * (unsigned long long)r;
        unsigned psz = (pp > (unsigned long long)(1u << 19)) ? (1u << 19) : (unsigned)pp;
        psz = (psz + 7u) / 8u * 8u;
        L.scale[l]  = (float)s;
        L.res[l]    = (unsigned)r;
        L.size[l]   = psz;
        L.offset[l] = off;
        L.hashed[l] = (pp > (unsigned long long)psz) ? 1u : 0u;
        off += psz;
    }

    int blocks = (N + 127) / 128;
    plane_kernel<<<blocks, 128>>>(sorted ? (const float2*)sxy_ptr : xy,
                                  sorted ? (const int*)perm_ptr : (const int*)nullptr,
                                  table, w0, w1, bound, bound_elems,
                                  (float*)d_out, N, L);
}

// round 14
// speedup vs baseline: 1.3356x; 1.3356x over previous
#include <cuda_runtime.h>
#include <cuda_fp16.h>
#include <math.h>

#define NLEV 16
#define RESO 2048
#define PRIME_Y 2654435761u
#define FSCALE 4096.0f
#define INV_FSCALE (1.0f / 4096.0f)

#define A_STRIDE_H 40   // halves per A row: banks (20g+tig)%32 distinct -> conflict-free
#define W_STRIDE_H 40

struct Levels {
    float    scale[NLEV];
    unsigned res[NLEV];
    unsigned size[NLEV];
    unsigned offset[NLEV];
};

typedef unsigned long long u64;
typedef unsigned int u32;

__device__ __forceinline__ u64 pk2(float lo, float hi) {
    u64 r; asm("mov.b64 %0,{%1,%2};" : "=l"(r) : "f"(lo), "f"(hi)); return r;
}
__device__ __forceinline__ float2 upk2(u64 a) {
    float2 f; asm("mov.b64 {%0,%1},%2;" : "=f"(f.x), "=f"(f.y) : "l"(a)); return f;
}
__device__ __forceinline__ u64 ffma2(u64 a, u64 b, u64 c) {
    u64 d; asm("fma.rn.f32x2 %0,%1,%2,%3;" : "=l"(d) : "l"(a), "l"(b), "l"(c)); return d;
}
__device__ __forceinline__ u64 mul2(u64 a, u64 b) {
    u64 d; asm("mul.rn.f32x2 %0,%1,%2;" : "=l"(d) : "l"(a), "l"(b)); return d;
}
__device__ __forceinline__ u32 cvt_h2(u64 pair) {
    float2 f = upk2(pair);
    __half2 hv = __floats2half2_rn(f.x, f.y);
    return *reinterpret_cast<u32*>(&hv);
}
__device__ __forceinline__ u32 cvt_h2f(float lo, float hi) {
    __half2 hv = __floats2half2_rn(lo, hi);
    return *reinterpret_cast<u32*>(&hv);
}

__device__ __forceinline__ float decode_bound(const unsigned* p, int elems) {
    if (!p || elems <= 0) return 1.0f;
    unsigned a = p[0];
    float ff = __uint_as_float(a);
    if (isfinite(ff) && fabsf(ff) > 1e-6f && fabsf(ff) < 1e9f) return ff;
    int ai = (int)a;
    if (ai != 0 && ai > -1000000000 && ai < 1000000000) return (float)ai;
    if (elems >= 2) {
        double d = __hiloint2double((int)p[1], (int)a);
        if (isfinite(d) && fabs(d) > 1e-6 && fabs(d) < 1e9) return (float)d;
    }
    return 1.0f;
}

__global__ __launch_bounds__(128, 4)
void plane_kernel(const float2* __restrict__ xy,
                  const float2* __restrict__ table,
                  const float*  __restrict__ w0g,
                  const float*  __restrict__ w1g,
                  const unsigned* __restrict__ bound_raw,
                  int bound_elems,
                  float* __restrict__ out,
                  int N, Levels L)
{
    __shared__ __align__(16) __half sA[4][128 * A_STRIDE_H];  // per-warp A staging
    __shared__ __align__(16) __half sW0h[64 * W_STRIDE_H];    // W0 fp16 [j][i]
    __shared__ __align__(16) __half sW1h[8 * 64];             // W1 hi fp16 [k][j]
    __shared__ __align__(16) __half sW1l[8 * 64];             // W1 lo fp16 (residual)

    const int tid = threadIdx.x;
    const int wid = tid >> 5;
    const int lid = tid & 31;
    const int g   = lid >> 2;   // groupID
    const int tig = lid & 3;    // threadID_in_group

    for (int i = tid; i < 64 * 32; i += 128) {
        int j = i >> 5, k = i & 31;
        sW0h[j * W_STRIDE_H + k] = __float2half(w0g[i]);
    }
    for (int i = tid; i < 8 * 64; i += 128) {
        float w = w1g[i];
        __half hi = __float2half(w);
        sW1h[i] = hi;
        sW1l[i] = __float2half(w - __half2float(hi));
    }
    __syncthreads();

    int n = blockIdx.x * 128 + tid;
    int nc = (n < N) ? n : (N - 1);

    float bound = decode_bound(bound_raw, bound_elems);

    float2 p = xy[nc];
    float inv2b = 0.5f / bound;
    float nxv = (p.x + bound) * inv2b;
    float nyv = (p.y + bound) * inv2b;
    float cxf = fminf(fmaxf(nxv * (float)RESO - 0.5f, 0.0f), (float)(RESO - 1));
    float cyf = fminf(fmaxf(nyv * (float)RESO - 0.5f, 0.0f), (float)(RESO - 1));
    float cx0 = floorf(cxf), cy0 = floorf(cyf);
    float cx1 = fminf(cx0 + 1.0f, (float)(RESO - 1));
    float cy1 = fminf(cy0 + 1.0f, (float)(RESO - 1));
    float u = cxf - cx0, v = cyf - cy0;

    float gx0 = (cx0 + 0.5f) * (1.0f / (float)RESO);
    float gx1 = (cx1 + 0.5f) * (1.0f / (float)RESO);
    float gyA = (cy0 + 0.5f) * (1.0f / (float)RESO);
    float gyB = (cy1 + 0.5f) * (1.0f / (float)RESO);

    __half* myA = sA[wid];

    // Encode in 4-level groups; stage each group's packed fp16 features so
    // only 16 packed regs are live. Hashed/dense split is COMPILE-TIME:
    // levels >= 12 are hashed (777^2 > 2^19; level 11: 562^2 << 2^19 —
    // ulp-robust boundary), so each unrolled iteration keeps one path only.
    #pragma unroll
    for (int lg = 0; lg < 4; lg++) {
        u32 Pa[4], Pb[4], Pc[4], Pd[4];
        #pragma unroll
        for (int li = 0; li < 4; li++) {
            const int l = lg * 4 + li;
            const bool hashed = (l >= 12);
            float    scale  = L.scale[l];
            unsigned res    = L.res[l];
            unsigned size   = L.size[l];
            unsigned off    = L.offset[l];

            float pxa = fmaf(gx0, scale, 0.5f);
            float pxb = fmaf(gx1, scale, 0.5f);
            float pya = fmaf(gyA, scale, 0.5f);
            float pyb = fmaf(gyB, scale, 0.5f);
            float fxa = floorf(pxa), fxb = floorf(pxb);
            float fya = floorf(pya), fyb = floorf(pyb);
            float ua1 = pxa - fxa, ua0 = 1.0f - ua1;
            float ub1 = pxb - fxb, ub0 = 1.0f - ub1;
            float va1 = (pya - fya) * FSCALE, va0 = FSCALE - va1;
            float vb1 = (pyb - fyb) * FSCALE, vb0 = FSCALE - vb1;
            unsigned ix = (unsigned)fxa, iy = (unsigned)fya;
            bool bdx = fxb > fxa;
            bool bdy = fyb > fya;

            unsigned i00, i01, i02, i10, i11, i12, i20, i21, i22;
            if (hashed) {
                const unsigned m = (1u << 19) - 1u;   // hashed size is always 2^19
                unsigned hy0 = iy * PRIME_Y, hy1 = hy0 + PRIME_Y, hy2 = hy1 + PRIME_Y;
                i00 = (ix ^ hy0) & m; i01 = ((ix + 1u) ^ hy0) & m; i02 = ((ix + 2u) ^ hy0) & m;
                i10 = (ix ^ hy1) & m; i11 = ((ix + 1u) ^ hy1) & m; i12 = ((ix + 2u) ^ hy1) & m;
                i20 = (ix ^ hy2) & m; i21 = ((ix + 1u) ^ hy2) & m; i22 = ((ix + 2u) ^ hy2) & m;
            } else {
                unsigned hy0 = iy * res, hy1 = hy0 + res, hy2 = hy1 + res;
                i00 = ix + hy0;      if (i00 >= size) i00 -= size;
                i01 = ix + 1u + hy0; if (i01 >= size) i01 -= size;
                i02 = ix + 2u + hy0; if (i02 >= size) i02 -= size;
                i10 = ix + hy1;      if (i10 >= size) i10 -= size;
                i11 = ix + 1u + hy1; if (i11 >= size) i11 -= size;
                i12 = ix + 2u + hy1; if (i12 >= size) i12 -= size;
                i20 = ix + hy2;      if (i20 >= size) i20 -= size;
                i21 = ix + 1u + hy2; if (i21 >= size) i21 -= size;
                i22 = ix + 2u + hy2; if (i22 >= size) i22 -= size;
            }

            const u64* tb = (const u64*)(table + off);
            u64 T00 = __ldg(tb + i00);
            u64 T01 = __ldg(tb + i01);
            u64 T10 = __ldg(tb + i10);
            u64 T11 = __ldg(tb + i11);
            u64 T02 = 0ull, T12 = 0ull, T20 = 0ull, T21 = 0ull, T22 = 0ull;
            if (bdx) { T02 = __ldg(tb + i02); T12 = __ldg(tb + i12); }
            if (bdy) { T20 = __ldg(tb + i20); T21 = __ldg(tb + i21); }
            if (bdx && bdy) { T22 = __ldg(tb + i22); }

            u64 ua0p = pk2(ua0, ua0), ua1p = pk2(ua1, ua1);
            u64 ub0p = pk2(ub0, ub0), ub1p = pk2(ub1, ub1);
            u64 va0p = pk2(va0, va0), va1p = pk2(va1, va1);
            u64 vb0p = pk2(vb0, vb0), vb1p = pk2(vb1, vb1);

            u64 S00 = ffma2(ua1p, T01, mul2(ua0p, T00));
            u64 S01 = ffma2(ua1p, T11, mul2(ua0p, T10));
            u64 S02 = ffma2(ua1p, T21, mul2(ua0p, T20));
            u64 X0r0 = bdx ? T01 : T00, X1r0 = bdx ? T02 : T01;
            u64 X0r1 = bdx ? T11 : T10, X1r1 = bdx ? T12 : T11;
            u64 X0r2 = bdx ? T21 : T20, X1r2 = bdx ? T22 : T21;
            u64 S10 = ffma2(ub1p, X1r0, mul2(ub0p, X0r0));
            u64 S11 = ffma2(ub1p, X1r1, mul2(ub0p, X0r1));
            u64 S12 = ffma2(ub1p, X1r2, mul2(ub0p, X0r2));

            Pa[li] = cvt_h2(ffma2(va1p, S01, mul2(va0p, S00)));
            Pb[li] = cvt_h2(ffma2(va1p, S11, mul2(va0p, S10)));
            u64 Y0a = bdy ? S01 : S00, Y1a = bdy ? S02 : S01;
            u64 Y0b = bdy ? S11 : S10, Y1b = bdy ? S12 : S11;
            Pc[li] = cvt_h2(ffma2(vb1p, Y1a, mul2(vb0p, Y0a)));
            Pd[li] = cvt_h2(ffma2(vb1p, Y1b, mul2(vb0p, Y0b)));
        }
        *(uint4*)(myA + (0 * 32 + lid) * A_STRIDE_H + lg * 8) = make_uint4(Pa[0], Pa[1], Pa[2], Pa[3]);
        *(uint4*)(myA + (1 * 32 + lid) * A_STRIDE_H + lg * 8) = make_uint4(Pb[0], Pb[1], Pb[2], Pb[3]);
        *(uint4*)(myA + (2 * 32 + lid) * A_STRIDE_H + lg * 8) = make_uint4(Pc[0], Pc[1], Pc[2], Pc[3]);
        *(uint4*)(myA + (3 * 32 + lid) * A_STRIDE_H + lg * 8) = make_uint4(Pd[0], Pd[1], Pd[2], Pd[3]);
    }
    __syncwarp();

    // Layer-1 B fragments (W0^T), per mma m16n8k16 spec; conflict-free.
    u32 Bf[2][8][2];
    #pragma unroll
    for (int kc = 0; kc < 2; kc++) {
        #pragma unroll
        for (int nt = 0; nt < 8; nt++) {
            const u32* wrow = (const u32*)&sW0h[(nt * 8 + g) * W_STRIDE_H + kc * 16];
            Bf[kc][nt][0] = wrow[tig];
            Bf[kc][nt][1] = wrow[tig + 4];
        }
    }
    // Layer-2 B fragments (m16n8k8), hi + lo split of W1 (fp16 W1 quantization
    // was the 7.2e-4 error source; split restores ~3e-4 total).
    u32 Bf2h[8], Bf2l[8];
    #pragma unroll
    for (int nt = 0; nt < 8; nt++) {
        Bf2h[nt] = *(const u32*)&sW1h[g * 64 + nt * 8 + tig * 2];
        Bf2l[nt] = *(const u32*)&sW1l[g * 64 + nt * 8 + tig * 2];
    }

    float cw[4];
    cw[0] = (1.0f - u) * (1.0f - v) * INV_FSCALE;
    cw[1] = u * (1.0f - v) * INV_FSCALE;
    cw[2] = (1.0f - u) * v * INV_FSCALE;
    cw[3] = u * v * INV_FSCALE;

    const int base = blockIdx.x * 128 + wid * 32;

    #pragma unroll
    for (int mtp = 0; mtp < 2; mtp++) {
        float hb[8][4];
        #pragma unroll
        for (int b = 0; b < 8; b++)
            #pragma unroll
            for (int c = 0; c < 4; c++) hb[b][c] = 0.0f;

        #pragma unroll
        for (int c = 0; c < 4; c++) {
            // D rows g / g+8 belong to points mtp*16+g / +8 -> fetch their
            // blend weights via shfl.
            float wlo = __shfl_sync(0xffffffffu, cw[c], mtp * 16 + g);
            float whi = __shfl_sync(0xffffffffu, cw[c], mtp * 16 + g + 8);

            u32 afr[2][4];
            #pragma unroll
            for (int kc = 0; kc < 2; kc++) {
                const __half* ar =
                    myA + (c * 32 + mtp * 16 + g) * A_STRIDE_H + kc * 16 + tig * 2;
                afr[kc][0] = *(const u32*)(ar);
                afr[kc][1] = *(const u32*)(ar + 8 * A_STRIDE_H);
                afr[kc][2] = *(const u32*)(ar + 8);
                afr[kc][3] = *(const u32*)(ar + 8 * A_STRIDE_H + 8);
            }
            #pragma unroll
            for (int nt = 0; nt < 8; nt++) {
                float d0 = 0.0f, d1 = 0.0f, d2 = 0.0f, d3 = 0.0f;
                asm volatile("mma.sync.aligned.m16n8k16.row.col.f32.f16.f16.f32 "
                    "{%0,%1,%2,%3},{%4,%5,%6,%7},{%8,%9},{%0,%1,%2,%3};"
                    : "+f"(d0), "+f"(d1), "+f"(d2), "+f"(d3)
                    : "r"(afr[0][0]), "r"(afr[0][1]), "r"(afr[0][2]), "r"(afr[0][3]),
                      "r"(Bf[0][nt][0]), "r"(Bf[0][nt][1]));
                asm volatile("mma.sync.aligned.m16n8k16.row.col.f32.f16.f16.f32 "
                    "{%0,%1,%2,%3},{%4,%5,%6,%7},{%8,%9},{%0,%1,%2,%3};"
                    : "+f"(d0), "+f"(d1), "+f"(d2), "+f"(d3)
                    : "r"(afr[1][0]), "r"(afr[1][1]), "r"(afr[1][2]), "r"(afr[1][3]),
                      "r"(Bf[1][nt][0]), "r"(Bf[1][nt][1]));
                hb[nt][0] = fmaf(fmaxf(d0, 0.0f), wlo, hb[nt][0]);
                hb[nt][1] = fmaf(fmaxf(d1, 0.0f), wlo, hb[nt][1]);
                hb[nt][2] = fmaf(fmaxf(d2, 0.0f), whi, hb[nt][2]);
                hb[nt][3] = fmaf(fmaxf(d3, 0.0f), whi, hb[nt][3]);
            }
        }

        // Layer 2 as MMA with hi+lo W1.
        float o0 = 0.0f, o1 = 0.0f, o2 = 0.0f, o3 = 0.0f;
        #pragma unroll
        for (int nt = 0; nt < 8; nt++) {
            u32 a0 = cvt_h2f(hb[nt][0], hb[nt][1]);
            u32 a1 = cvt_h2f(hb[nt][2], hb[nt][3]);
            asm volatile("mma.sync.aligned.m16n8k8.row.col.f32.f16.f16.f32 "
                "{%0,%1,%2,%3},{%4,%5},{%6},{%0,%1,%2,%3};"
                : "+f"(o0), "+f"(o1), "+f"(o2), "+f"(o3)
                : "r"(a0), "r"(a1), "r"(Bf2h[nt]));
            asm volatile("mma.sync.aligned.m16n8k8.row.col.f32.f16.f16.f32 "
                "{%0,%1,%2,%3},{%4,%5},{%6},{%0,%1,%2,%3};"
                : "+f"(o0), "+f"(o1), "+f"(o2), "+f"(o3)
                : "r"(a0), "r"(a1), "r"(Bf2l[nt]));
        }

        int pt0 = base + mtp * 16 + g;
        if (pt0 < N)
            *(float2*)(out + (size_t)pt0 * 8 + 2 * tig) = make_float2(o0, o1);
        int pt1 = pt0 + 8;
        if (pt1 < N)
            *(float2*)(out + (size_t)pt1 * 8 + 2 * tig) = make_float2(o2, o3);
    }
}

extern "C" void kernel_launch(void* const* d_in, const int* in_sizes, int n_in,
                              void* d_out, int out_size)
{
    const float2* xy    = (const float2*)d_in[0];
    const float2* table = (const float2*)d_in[1];
    const float*  w0    = (const float*)d_in[2];
    const float*  w1    = (const float*)d_in[3];
    const unsigned* bound = (n_in > 4) ? (const unsigned*)d_in[4] : nullptr;
    int bound_elems = (n_in > 4) ? in_sizes[4] : 0;

    int N = in_sizes[0] / 2;

    // Level constants — same double-precision libm sequence as the numpy
    // reference so ceil() boundaries match exactly.
    Levels L;
    double b = exp2(log2(2048.0 / 16.0) / 15.0);
    unsigned off = 0;
    for (int l = 0; l < NLEV; l++) {
        double s = 16.0 * pow(b, (double)l) - 1.0;
        int r = (int)ceil(s) + 1;
        unsigned long long pp = (unsigned long long)r * (unsigned long long)r;
        unsigned psz = (pp > (unsigned long long)(1u << 19)) ? (1u << 19) : (unsigned)pp;
        psz = (psz + 7u) / 8u * 8u;
        L.scale[l]  = (float)s;
        L.res[l]    = (unsigned)r;
        L.size[l]   = psz;
        L.offset[l] = off;
        off += psz;
    }

    int blocks = (N + 127) / 128;
    plane_kernel<<<blocks, 128>>>(xy, table, w0, w1, bound, bound_elems,
                                  (float*)d_out, N, L);
}

// round 15
// speedup vs baseline: 1.4919x; 1.1170x over previous
#include <cuda_runtime.h>
#include <cuda_fp16.h>
#include <math.h>

#define NLEV 16
#define RESO 2048
#define PRIME_Y 2654435761u
#define FSCALE 4096.0f
#define INV_FSCALE (1.0f / 4096.0f)

#define A_STRIDE_H 40   // halves per A row: banks (20g+tig)%32 distinct -> conflict-free
#define W_STRIDE_H 40

struct Levels {
    float    scale[NLEV];
    unsigned res[NLEV];
    unsigned size[NLEV];
    unsigned offset[NLEV];
    unsigned hashed[NLEV];
};

typedef unsigned long long u64;
typedef unsigned int u32;

__device__ __forceinline__ u64 pk2(float lo, float hi) {
    u64 r; asm("mov.b64 %0,{%1,%2};" : "=l"(r) : "f"(lo), "f"(hi)); return r;
}
__device__ __forceinline__ float2 upk2(u64 a) {
    float2 f; asm("mov.b64 {%0,%1},%2;" : "=f"(f.x), "=f"(f.y) : "l"(a)); return f;
}
__device__ __forceinline__ u64 ffma2(u64 a, u64 b, u64 c) {
    u64 d; asm("fma.rn.f32x2 %0,%1,%2,%3;" : "=l"(d) : "l"(a), "l"(b), "l"(c)); return d;
}
__device__ __forceinline__ u64 mul2(u64 a, u64 b) {
    u64 d; asm("mul.rn.f32x2 %0,%1,%2;" : "=l"(d) : "l"(a), "l"(b)); return d;
}
__device__ __forceinline__ u32 cvt_h2(u64 pair) {
    float2 f = upk2(pair);
    __half2 hv = __floats2half2_rn(f.x, f.y);
    return *reinterpret_cast<u32*>(&hv);
}
__device__ __forceinline__ u32 cvt_h2f(float lo, float hi) {
    __half2 hv = __floats2half2_rn(lo, hi);
    return *reinterpret_cast<u32*>(&hv);
}

__device__ __forceinline__ float decode_bound(const unsigned* p, int elems) {
    if (!p || elems <= 0) return 1.0f;
    unsigned a = p[0];
    float ff = __uint_as_float(a);
    if (isfinite(ff) && fabsf(ff) > 1e-6f && fabsf(ff) < 1e9f) return ff;
    int ai = (int)a;
    if (ai != 0 && ai > -1000000000 && ai < 1000000000) return (float)ai;
    if (elems >= 2) {
        double d = __hiloint2double((int)p[1], (int)a);
        if (isfinite(d) && fabs(d) > 1e-6 && fabs(d) < 1e9) return (float)d;
    }
    return 1.0f;
}

__global__ __launch_bounds__(128, 4)
void plane_kernel(const float2* __restrict__ xy,
                  const float2* __restrict__ table,
                  const float*  __restrict__ w0g,
                  const float*  __restrict__ w1g,
                  const unsigned* __restrict__ bound_raw,
                  int bound_elems,
                  float* __restrict__ out,
                  int N, Levels L)
{
    __shared__ __align__(16) __half sA[4][128 * A_STRIDE_H];  // per-warp A staging
    __shared__ __align__(16) __half sW0h[64 * W_STRIDE_H];    // W0 fp16 [j][i]
    __shared__ __align__(16) __half sW1h[8 * 64];             // W1 hi fp16 [k][j]
    __shared__ __align__(16) __half sW1l[8 * 64];             // W1 lo fp16 (residual)

    const int tid = threadIdx.x;
    const int wid = tid >> 5;
    const int lid = tid & 31;
    const int g   = lid >> 2;   // groupID
    const int tig = lid & 3;    // threadID_in_group

    for (int i = tid; i < 64 * 32; i += 128) {
        int j = i >> 5, k = i & 31;
        sW0h[j * W_STRIDE_H + k] = __float2half(w0g[i]);
    }
    for (int i = tid; i < 8 * 64; i += 128) {
        float w = w1g[i];
        __half hi = __float2half(w);
        sW1h[i] = hi;
        sW1l[i] = __float2half(w - __half2float(hi));
    }
    __syncthreads();

    int n = blockIdx.x * 128 + tid;
    int nc = (n < N) ? n : (N - 1);

    float bound = decode_bound(bound_raw, bound_elems);

    float2 p = xy[nc];
    float inv2b = 0.5f / bound;
    float nxv = (p.x + bound) * inv2b;
    float nyv = (p.y + bound) * inv2b;
    float cxf = fminf(fmaxf(nxv * (float)RESO - 0.5f, 0.0f), (float)(RESO - 1));
    float cyf = fminf(fmaxf(nyv * (float)RESO - 0.5f, 0.0f), (float)(RESO - 1));
    float cx0 = floorf(cxf), cy0 = floorf(cyf);
    float cx1 = fminf(cx0 + 1.0f, (float)(RESO - 1));
    float cy1 = fminf(cy0 + 1.0f, (float)(RESO - 1));
    float u = cxf - cx0, v = cyf - cy0;

    float gx0 = (cx0 + 0.5f) * (1.0f / (float)RESO);
    float gx1 = (cx1 + 0.5f) * (1.0f / (float)RESO);
    float gyA = (cy0 + 0.5f) * (1.0f / (float)RESO);
    float gyB = (cy1 + 0.5f) * (1.0f / (float)RESO);

    __half* myA = sA[wid];

    // Encode in 4-level groups; stage each group's packed fp16 features so
    // only 16 packed feature regs are live. (Runtime hashed flag — the
    // compile-time split regressed in R14; keep R12's exact code layout.)
    #pragma unroll
    for (int lg = 0; lg < 4; lg++) {
        u32 Pa[4], Pb[4], Pc[4], Pd[4];
        #pragma unroll
        for (int li = 0; li < 4; li++) {
            const int l = lg * 4 + li;
            float    scale  = L.scale[l];
            unsigned res    = L.res[l];
            unsigned size   = L.size[l];
            unsigned off    = L.offset[l];
            bool     hashed = (L.hashed[l] != 0);

            float pxa = fmaf(gx0, scale, 0.5f);
            float pxb = fmaf(gx1, scale, 0.5f);
            float pya = fmaf(gyA, scale, 0.5f);
            float pyb = fmaf(gyB, scale, 0.5f);
            float fxa = floorf(pxa), fxb = floorf(pxb);
            float fya = floorf(pya), fyb = floorf(pyb);
            float ua1 = pxa - fxa, ua0 = 1.0f - ua1;
            float ub1 = pxb - fxb, ub0 = 1.0f - ub1;
            float va1 = (pya - fya) * FSCALE, va0 = FSCALE - va1;
            float vb1 = (pyb - fyb) * FSCALE, vb0 = FSCALE - vb1;
            unsigned ix = (unsigned)fxa, iy = (unsigned)fya;
            bool bdx = fxb > fxa;
            bool bdy = fyb > fya;

            unsigned i00, i01, i02, i10, i11, i12, i20, i21, i22;
            if (hashed) {
                unsigned m = size - 1u;
                unsigned hy0 = iy * PRIME_Y, hy1 = hy0 + PRIME_Y, hy2 = hy1 + PRIME_Y;
                i00 = (ix ^ hy0) & m; i01 = ((ix + 1u) ^ hy0) & m; i02 = ((ix + 2u) ^ hy0) & m;
                i10 = (ix ^ hy1) & m; i11 = ((ix + 1u) ^ hy1) & m; i12 = ((ix + 2u) ^ hy1) & m;
                i20 = (ix ^ hy2) & m; i21 = ((ix + 1u) ^ hy2) & m; i22 = ((ix + 2u) ^ hy2) & m;
            } else {
                unsigned hy0 = iy * res, hy1 = hy0 + res, hy2 = hy1 + res;
                i00 = ix + hy0;      if (i00 >= size) i00 -= size;
                i01 = ix + 1u + hy0; if (i01 >= size) i01 -= size;
                i02 = ix + 2u + hy0; if (i02 >= size) i02 -= size;
                i10 = ix + hy1;      if (i10 >= size) i10 -= size;
                i11 = ix + 1u + hy1; if (i11 >= size) i11 -= size;
                i12 = ix + 2u + hy1; if (i12 >= size) i12 -= size;
                i20 = ix + hy2;      if (i20 >= size) i20 -= size;
                i21 = ix + 1u + hy2; if (i21 >= size) i21 -= size;
                i22 = ix + 2u + hy2; if (i22 >= size) i22 -= size;
            }

            const u64* tb = (const u64*)(table + off);
            u64 T00 = __ldg(tb + i00);
            u64 T01 = __ldg(tb + i01);
            u64 T10 = __ldg(tb + i10);
            u64 T11 = __ldg(tb + i11);
            u64 T02 = 0ull, T12 = 0ull, T20 = 0ull, T21 = 0ull, T22 = 0ull;
            if (bdx) { T02 = __ldg(tb + i02); T12 = __ldg(tb + i12); }
            if (bdy) { T20 = __ldg(tb + i20); T21 = __ldg(tb + i21); }
            if (bdx && bdy) { T22 = __ldg(tb + i22); }

            u64 ua0p = pk2(ua0, ua0), ua1p = pk2(ua1, ua1);
            u64 ub0p = pk2(ub0, ub0), ub1p = pk2(ub1, ub1);
            u64 va0p = pk2(va0, va0), va1p = pk2(va1, va1);
            u64 vb0p = pk2(vb0, vb0), vb1p = pk2(vb1, vb1);

            u64 S00 = ffma2(ua1p, T01, mul2(ua0p, T00));
            u64 S01 = ffma2(ua1p, T11, mul2(ua0p, T10));
            u64 S02 = ffma2(ua1p, T21, mul2(ua0p, T20));
            u64 X0r0 = bdx ? T01 : T00, X1r0 = bdx ? T02 : T01;
            u64 X0r1 = bdx ? T11 : T10, X1r1 = bdx ? T12 : T11;
            u64 X0r2 = bdx ? T21 : T20, X1r2 = bdx ? T22 : T21;
            u64 S10 = ffma2(ub1p, X1r0, mul2(ub0p, X0r0));
            u64 S11 = ffma2(ub1p, X1r1, mul2(ub0p, X0r1));
            u64 S12 = ffma2(ub1p, X1r2, mul2(ub0p, X0r2));

            Pa[li] = cvt_h2(ffma2(va1p, S01, mul2(va0p, S00)));
            Pb[li] = cvt_h2(ffma2(va1p, S11, mul2(va0p, S10)));
            u64 Y0a = bdy ? S01 : S00, Y1a = bdy ? S02 : S01;
            u64 Y0b = bdy ? S11 : S10, Y1b = bdy ? S12 : S11;
            Pc[li] = cvt_h2(ffma2(vb1p, Y1a, mul2(vb0p, Y0a)));
            Pd[li] = cvt_h2(ffma2(vb1p, Y1b, mul2(vb0p, Y0b)));
        }
        *(uint4*)(myA + (0 * 32 + lid) * A_STRIDE_H + lg * 8) = make_uint4(Pa[0], Pa[1], Pa[2], Pa[3]);
        *(uint4*)(myA + (1 * 32 + lid) * A_STRIDE_H + lg * 8) = make_uint4(Pb[0], Pb[1], Pb[2], Pb[3]);
        *(uint4*)(myA + (2 * 32 + lid) * A_STRIDE_H + lg * 8) = make_uint4(Pc[0], Pc[1], Pc[2], Pc[3]);
        *(uint4*)(myA + (3 * 32 + lid) * A_STRIDE_H + lg * 8) = make_uint4(Pd[0], Pd[1], Pd[2], Pd[3]);
    }
    __syncwarp();

    // Layer-1 B fragments (W0^T), per mma m16n8k16 spec; conflict-free.
    u32 Bf[2][8][2];
    #pragma unroll
    for (int kc = 0; kc < 2; kc++) {
        #pragma unroll
        for (int nt = 0; nt < 8; nt++) {
            const u32* wrow = (const u32*)&sW0h[(nt * 8 + g) * W_STRIDE_H + kc * 16];
            Bf[kc][nt][0] = wrow[tig];
            Bf[kc][nt][1] = wrow[tig + 4];
        }
    }
    // Layer-2 B fragments (m16n8k8), hi + lo split of W1.
    u32 Bf2h[8], Bf2l[8];
    #pragma unroll
    for (int nt = 0; nt < 8; nt++) {
        Bf2h[nt] = *(const u32*)&sW1h[g * 64 + nt * 8 + tig * 2];
        Bf2l[nt] = *(const u32*)&sW1l[g * 64 + nt * 8 + tig * 2];
    }

    // cw WITHOUT INV_FSCALE: hb stays in fp16-normal range (~O(1)), so both
    // the hi fp16 value and its residual are representable. The 1/FSCALE is
    // folded into the final output write.
    float cw[4];
    cw[0] = (1.0f - u) * (1.0f - v);
    cw[1] = u * (1.0f - v);
    cw[2] = (1.0f - u) * v;
    cw[3] = u * v;

    const int base = blockIdx.x * 128 + wid * 32;

    #pragma unroll
    for (int mtp = 0; mtp < 2; mtp++) {
        float hb[8][4];
        #pragma unroll
        for (int b = 0; b < 8; b++)
            #pragma unroll
            for (int c = 0; c < 4; c++) hb[b][c] = 0.0f;

        #pragma unroll
        for (int c = 0; c < 4; c++) {
            // D rows g / g+8 belong to points mtp*16+g / +8 -> fetch their
            // blend weights via shfl.
            float wlo = __shfl_sync(0xffffffffu, cw[c], mtp * 16 + g);
            float whi = __shfl_sync(0xffffffffu, cw[c], mtp * 16 + g + 8);

            u32 afr[2][4];
            #pragma unroll
            for (int kc = 0; kc < 2; kc++) {
                const __half* ar =
                    myA + (c * 32 + mtp * 16 + g) * A_STRIDE_H + kc * 16 + tig * 2;
                afr[kc][0] = *(const u32*)(ar);
                afr[kc][1] = *(const u32*)(ar + 8 * A_STRIDE_H);
                afr[kc][2] = *(const u32*)(ar + 8);
                afr[kc][3] = *(const u32*)(ar + 8 * A_STRIDE_H + 8);
            }
            #pragma unroll
            for (int nt = 0; nt < 8; nt++) {
                float d0 = 0.0f, d1 = 0.0f, d2 = 0.0f, d3 = 0.0f;
                asm volatile("mma.sync.aligned.m16n8k16.row.col.f32.f16.f16.f32 "
                    "{%0,%1,%2,%3},{%4,%5,%6,%7},{%8,%9},{%0,%1,%2,%3};"
                    : "+f"(d0), "+f"(d1), "+f"(d2), "+f"(d3)
                    : "r"(afr[0][0]), "r"(afr[0][1]), "r"(afr[0][2]), "r"(afr[0][3]),
                      "r"(Bf[0][nt][0]), "r"(Bf[0][nt][1]));
                asm volatile("mma.sync.aligned.m16n8k16.row.col.f32.f16.f16.f32 "
                    "{%0,%1,%2,%3},{%4,%5,%6,%7},{%8,%9},{%0,%1,%2,%3};"
                    : "+f"(d0), "+f"(d1), "+f"(d2), "+f"(d3)
                    : "r"(afr[1][0]), "r"(afr[1][1]), "r"(afr[1][2]), "r"(afr[1][3]),
                      "r"(Bf[1][nt][0]), "r"(Bf[1][nt][1]));
                hb[nt][0] = fmaf(fmaxf(d0, 0.0f), wlo, hb[nt][0]);
                hb[nt][1] = fmaf(fmaxf(d1, 0.0f), wlo, hb[nt][1]);
                hb[nt][2] = fmaf(fmaxf(d2, 0.0f), whi, hb[nt][2]);
                hb[nt][3] = fmaf(fmaxf(d3, 0.0f), whi, hb[nt][3]);
            }
        }

        // Layer 2 as MMA, 3-term split: h_hi*w_hi + h_lo*w_hi + h_hi*w_lo.
        // With rescaled h, h_lo (~2e-4) is representable fp16; w_lo only
        // needs ~1% relative accuracy, so fp16 denormals suffice.
        float o0 = 0.0f, o1 = 0.0f, o2 = 0.0f, o3 = 0.0f;
        #pragma unroll
        for (int nt = 0; nt < 8; nt++) {
            __half2 h01 = __floats2half2_rn(hb[nt][0], hb[nt][1]);
            __half2 h23 = __floats2half2_rn(hb[nt][2], hb[nt][3]);
            float2 f01 = __half22float2(h01);
            float2 f23 = __half22float2(h23);
            u32 a0  = *reinterpret_cast<u32*>(&h01);
            u32 a1  = *reinterpret_cast<u32*>(&h23);
            u32 a0l = cvt_h2f(hb[nt][0] - f01.x, hb[nt][1] - f01.y);
            u32 a1l = cvt_h2f(hb[nt][2] - f23.x, hb[nt][3] - f23.y);
            asm volatile("mma.sync.aligned.m16n8k8.row.col.f32.f16.f16.f32 "
                "{%0,%1,%2,%3},{%4,%5},{%6},{%0,%1,%2,%3};"
                : "+f"(o0), "+f"(o1), "+f"(o2), "+f"(o3)
                : "r"(a0), "r"(a1), "r"(Bf2h[nt]));
            asm volatile("mma.sync.aligned.m16n8k8.row.col.f32.f16.f16.f32 "
                "{%0,%1,%2,%3},{%4,%5},{%6},{%0,%1,%2,%3};"
                : "+f"(o0), "+f"(o1), "+f"(o2), "+f"(o3)
                : "r"(a0l), "r"(a1l), "r"(Bf2h[nt]));
            asm volatile("mma.sync.aligned.m16n8k8.row.col.f32.f16.f16.f32 "
                "{%0,%1,%2,%3},{%4,%5},{%6},{%0,%1,%2,%3};"
                : "+f"(o0), "+f"(o1), "+f"(o2), "+f"(o3)
                : "r"(a0), "r"(a1), "r"(Bf2l[nt]));
        }
        o0 *= INV_FSCALE; o1 *= INV_FSCALE;
        o2 *= INV_FSCALE; o3 *= INV_FSCALE;

        int pt0 = base + mtp * 16 + g;
        if (pt0 < N)
            *(float2*)(out + (size_t)pt0 * 8 + 2 * tig) = make_float2(o0, o1);
        int pt1 = pt0 + 8;
        if (pt1 < N)
            *(float2*)(out + (size_t)pt1 * 8 + 2 * tig) = make_float2(o2, o3);
    }
}

extern "C" void kernel_launch(void* const* d_in, const int* in_sizes, int n_in,
                              void* d_out, int out_size)
{
    const float2* xy    = (const float2*)d_in[0];
    const float2* table = (const float2*)d_in[1];
    const float*  w0    = (const float*)d_in[2];
    const float*  w1    = (const float*)d_in[3];
    const unsigned* bound = (n_in > 4) ? (const unsigned*)d_in[4] : nullptr;
    int bound_elems = (n_in > 4) ? in_sizes[4] : 0;

    int N = in_sizes[0] / 2;

    // Level constants — same double-precision libm sequence as the numpy
    // reference so ceil() boundaries match exactly.
    Levels L;
    double b = exp2(log2(2048.0 / 16.0) / 15.0);
    unsigned off = 0;
    for (int l = 0; l < NLEV; l++) {
        double s = 16.0 * pow(b, (double)l) - 1.0;
        int r = (int)ceil(s) + 1;
        unsigned long long pp = (unsigned long long)r * (unsigned long long)r;
        unsigned psz = (pp > (unsigned long long)(1u << 19)) ? (1u << 19) : (unsigned)pp;
        psz = (psz + 7u) / 8u * 8u;
        L.scale[l]  = (float)s;
        L.res[l]    = (unsigned)r;
        L.size[l]   = psz;
        L.offset[l] = off;
        L.hashed[l] = (pp > (unsigned long long)psz) ? 1u : 0u;
        off += psz;
    }

    int blocks = (N + 127) / 128;
    plane_kernel<<<blocks, 128>>>(xy, table, w0, w1, bound, bound_elems,
                                  (float*)d_out, N, L);
}

// round 16
// speedup vs baseline: 1.5980x; 1.0711x over previous
#include <cuda_runtime.h>
#include <cuda_fp16.h>
#include <math.h>

#define NLEV 16
#define RESO 2048
#define PRIME_Y 2654435761u
#define FSCALE 4096.0f
#define INV_FSCALE (1.0f / 4096.0f)

#define A_STRIDE_H 40   // halves per A row: banks (20g+tig)%32 distinct -> conflict-free
#define W_STRIDE_H 40

struct Levels {
    float    scale[NLEV];
    unsigned res[NLEV];
    unsigned size[NLEV];
    unsigned offset[NLEV];
    unsigned hashed[NLEV];
};

typedef unsigned long long u64;
typedef unsigned int u32;

__device__ __forceinline__ u64 pk2(float lo, float hi) {
    u64 r; asm("mov.b64 %0,{%1,%2};" : "=l"(r) : "f"(lo), "f"(hi)); return r;
}
__device__ __forceinline__ float2 upk2(u64 a) {
    float2 f; asm("mov.b64 {%0,%1},%2;" : "=f"(f.x), "=f"(f.y) : "l"(a)); return f;
}
__device__ __forceinline__ u64 ffma2(u64 a, u64 b, u64 c) {
    u64 d; asm("fma.rn.f32x2 %0,%1,%2,%3;" : "=l"(d) : "l"(a), "l"(b), "l"(c)); return d;
}
__device__ __forceinline__ u64 mul2(u64 a, u64 b) {
    u64 d; asm("mul.rn.f32x2 %0,%1,%2;" : "=l"(d) : "l"(a), "l"(b)); return d;
}
__device__ __forceinline__ u32 cvt_h2(u64 pair) {
    float2 f = upk2(pair);
    __half2 hv = __floats2half2_rn(f.x, f.y);
    return *reinterpret_cast<u32*>(&hv);
}
__device__ __forceinline__ u32 cvt_h2f(float lo, float hi) {
    __half2 hv = __floats2half2_rn(lo, hi);
    return *reinterpret_cast<u32*>(&hv);
}

__device__ __forceinline__ float decode_bound(const unsigned* p, int elems) {
    if (!p || elems <= 0) return 1.0f;
    unsigned a = p[0];
    float ff = __uint_as_float(a);
    if (isfinite(ff) && fabsf(ff) > 1e-6f && fabsf(ff) < 1e9f) return ff;
    int ai = (int)a;
    if (ai != 0 && ai > -1000000000 && ai < 1000000000) return (float)ai;
    if (elems >= 2) {
        double d = __hiloint2double((int)p[1], (int)a);
        if (isfinite(d) && fabs(d) > 1e-6 && fabs(d) < 1e9) return (float)d;
    }
    return 1.0f;
}

__global__ __launch_bounds__(128, 4)
void plane_kernel(const float2* __restrict__ xy,
                  const float2* __restrict__ table,
                  const float*  __restrict__ w0g,
                  const float*  __restrict__ w1g,
                  const unsigned* __restrict__ bound_raw,
                  int bound_elems,
                  float* __restrict__ out,
                  int N, Levels L)
{
    __shared__ __align__(16) __half sA[4][128 * A_STRIDE_H];  // per-warp A staging
    __shared__ __align__(16) __half sW0h[64 * W_STRIDE_H];    // W0 fp16 [j][i]
    __shared__ __align__(16) __half sW1h[8 * 64];             // W1 hi fp16 [k][j]
    __shared__ __align__(16) __half sW1l[8 * 64];             // W1 lo fp16 (residual)

    const int tid = threadIdx.x;
    const int wid = tid >> 5;
    const int lid = tid & 31;
    const int g   = lid >> 2;   // groupID
    const int tig = lid & 3;    // threadID_in_group

    for (int i = tid; i < 64 * 32; i += 128) {
        int j = i >> 5, k = i & 31;
        sW0h[j * W_STRIDE_H + k] = __float2half(w0g[i]);
    }
    for (int i = tid; i < 8 * 64; i += 128) {
        float w = w1g[i];
        __half hi = __float2half(w);
        sW1h[i] = hi;
        sW1l[i] = __float2half(w - __half2float(hi));
    }
    __syncthreads();

    int n = blockIdx.x * 128 + tid;
    int nc = (n < N) ? n : (N - 1);

    float bound = decode_bound(bound_raw, bound_elems);

    float2 p = xy[nc];
    float inv2b = 0.5f / bound;
    float nxv = (p.x + bound) * inv2b;
    float nyv = (p.y + bound) * inv2b;
    float cxf = fminf(fmaxf(nxv * (float)RESO - 0.5f, 0.0f), (float)(RESO - 1));
    float cyf = fminf(fmaxf(nyv * (float)RESO - 0.5f, 0.0f), (float)(RESO - 1));
    float cx0 = floorf(cxf), cy0 = floorf(cyf);
    float cx1 = fminf(cx0 + 1.0f, (float)(RESO - 1));
    float cy1 = fminf(cy0 + 1.0f, (float)(RESO - 1));
    float u = cxf - cx0, v = cyf - cy0;

    float gx0 = (cx0 + 0.5f) * (1.0f / (float)RESO);
    float gx1 = (cx1 + 0.5f) * (1.0f / (float)RESO);
    float gyA = (cy0 + 0.5f) * (1.0f / (float)RESO);
    float gyB = (cy1 + 0.5f) * (1.0f / (float)RESO);

    __half* myA = sA[wid];

    // Encode in 4-level groups; stage each group's packed fp16 features so
    // only 16 packed feature regs are live.
    #pragma unroll
    for (int lg = 0; lg < 4; lg++) {
        u32 Pa[4], Pb[4], Pc[4], Pd[4];
        #pragma unroll
        for (int li = 0; li < 4; li++) {
            const int l = lg * 4 + li;
            float    scale  = L.scale[l];
            unsigned res    = L.res[l];
            unsigned size   = L.size[l];
            unsigned off    = L.offset[l];
            bool     hashed = (L.hashed[l] != 0);

            float pxa = fmaf(gx0, scale, 0.5f);
            float pxb = fmaf(gx1, scale, 0.5f);
            float pya = fmaf(gyA, scale, 0.5f);
            float pyb = fmaf(gyB, scale, 0.5f);
            float fxa = floorf(pxa), fxb = floorf(pxb);
            float fya = floorf(pya), fyb = floorf(pyb);
            float ua1 = pxa - fxa, ua0 = 1.0f - ua1;
            float ub1 = pxb - fxb, ub0 = 1.0f - ub1;
            float va1 = (pya - fya) * FSCALE, va0 = FSCALE - va1;
            float vb1 = (pyb - fyb) * FSCALE, vb0 = FSCALE - vb1;
            unsigned ix = (unsigned)fxa, iy = (unsigned)fya;
            bool bdx = fxb > fxa;
            bool bdy = fyb > fya;

            u64 T00, T01, T02, T10, T11, T12, T20, T21, T22;

            if (hashed) {
                unsigned m = size - 1u;
                unsigned hy0 = iy * PRIME_Y, hy1 = hy0 + PRIME_Y, hy2 = hy1 + PRIME_Y;
                unsigned i00 = (ix ^ hy0) & m, i01 = ((ix + 1u) ^ hy0) & m, i02 = ((ix + 2u) ^ hy0) & m;
                unsigned i10 = (ix ^ hy1) & m, i11 = ((ix + 1u) ^ hy1) & m, i12 = ((ix + 2u) ^ hy1) & m;
                unsigned i20 = (ix ^ hy2) & m, i21 = ((ix + 1u) ^ hy2) & m, i22 = ((ix + 2u) ^ hy2) & m;
                const u64* tb = (const u64*)(table + off);
                T00 = __ldg(tb + i00);
                T01 = __ldg(tb + i01);
                T10 = __ldg(tb + i10);
                T11 = __ldg(tb + i11);
                T02 = 0ull; T12 = 0ull; T20 = 0ull; T21 = 0ull; T22 = 0ull;
                if (bdx) { T02 = __ldg(tb + i02); T12 = __ldg(tb + i12); }
                if (bdy) { T20 = __ldg(tb + i20); T21 = __ldg(tb + i21); }
                if (bdx && bdy) { T22 = __ldg(tb + i22); }
            } else {
                // Dense level: a row's 3 taps are CONTIGUOUS entries. Load the
                // aligned 16B pair (2 entries) and, only when needed
                // (odd base or bdx), the next pair. Row base wrapped once
                // (uniform shift keeps contiguity); size is even so pairs
                // never straddle; second-pair index wraps p+1==size/2 -> 0.
                // Entry selection by base parity; bit-identical results.
                unsigned hy0 = iy * res, hy1 = hy0 + res, hy2 = hy1 + res;
                unsigned b0 = ix + hy0; if (b0 >= size) b0 -= size;
                unsigned b1 = ix + hy1; if (b1 >= size) b1 -= size;
                unsigned b2 = ix + hy2; if (b2 >= size) b2 -= size;
                unsigned half = size >> 1;
                unsigned p00 = b0 >> 1, p01 = (p00 + 1u == half) ? 0u : p00 + 1u;
                unsigned p10 = b1 >> 1, p11 = (p10 + 1u == half) ? 0u : p10 + 1u;
                unsigned p20 = b2 >> 1, p21 = (p20 + 1u == half) ? 0u : p20 + 1u;
                bool od0 = (b0 & 1u), od1 = (b1 & 1u), od2 = (b2 & 1u);
                const ulonglong2* tb2 = (const ulonglong2*)(table + off);

                ulonglong2 A0 = __ldg(tb2 + p00);
                ulonglong2 B0 = __ldg(tb2 + p10);
                ulonglong2 A1 = make_ulonglong2(0ull, 0ull);
                ulonglong2 B1 = make_ulonglong2(0ull, 0ull);
                ulonglong2 C0 = make_ulonglong2(0ull, 0ull);
                ulonglong2 C1 = make_ulonglong2(0ull, 0ull);
                if (od0 || bdx) A1 = __ldg(tb2 + p01);
                if (od1 || bdx) B1 = __ldg(tb2 + p11);
                if (bdy) {
                    C0 = __ldg(tb2 + p20);
                    if (od2 || bdx) C1 = __ldg(tb2 + p21);
                }

                T00 = od0 ? A0.y : A0.x;
                T01 = od0 ? A1.x : A0.y;
                T02 = od0 ? A1.y : A1.x;
                T10 = od1 ? B0.y : B0.x;
                T11 = od1 ? B1.x : B0.y;
                T12 = od1 ? B1.y : B1.x;
                T20 = od2 ? C0.y : C0.x;
                T21 = od2 ? C1.x : C0.y;
                T22 = od2 ? C1.y : C1.x;
            }

            u64 ua0p = pk2(ua0, ua0), ua1p = pk2(ua1, ua1);
            u64 ub0p = pk2(ub0, ub0), ub1p = pk2(ub1, ub1);
            u64 va0p = pk2(va0, va0), va1p = pk2(va1, va1);
            u64 vb0p = pk2(vb0, vb0), vb1p = pk2(vb1, vb1);

            u64 S00 = ffma2(ua1p, T01, mul2(ua0p, T00));
            u64 S01 = ffma2(ua1p, T11, mul2(ua0p, T10));
            u64 S02 = ffma2(ua1p, T21, mul2(ua0p, T20));
            u64 X0r0 = bdx ? T01 : T00, X1r0 = bdx ? T02 : T01;
            u64 X0r1 = bdx ? T11 : T10, X1r1 = bdx ? T12 : T11;
            u64 X0r2 = bdx ? T21 : T20, X1r2 = bdx ? T22 : T21;
            u64 S10 = ffma2(ub1p, X1r0, mul2(ub0p, X0r0));
            u64 S11 = ffma2(ub1p, X1r1, mul2(ub0p, X0r1));
            u64 S12 = ffma2(ub1p, X1r2, mul2(ub0p, X0r2));

            Pa[li] = cvt_h2(ffma2(va1p, S01, mul2(va0p, S00)));
            Pb[li] = cvt_h2(ffma2(va1p, S11, mul2(va0p, S10)));
            u64 Y0a = bdy ? S01 : S00, Y1a = bdy ? S02 : S01;
            u64 Y0b = bdy ? S11 : S10, Y1b = bdy ? S12 : S11;
            Pc[li] = cvt_h2(ffma2(vb1p, Y1a, mul2(vb0p, Y0a)));
            Pd[li] = cvt_h2(ffma2(vb1p, Y1b, mul2(vb0p, Y0b)));
        }
        *(uint4*)(myA + (0 * 32 + lid) * A_STRIDE_H + lg * 8) = make_uint4(Pa[0], Pa[1], Pa[2], Pa[3]);
        *(uint4*)(myA + (1 * 32 + lid) * A_STRIDE_H + lg * 8) = make_uint4(Pb[0], Pb[1], Pb[2], Pb[3]);
        *(uint4*)(myA + (2 * 32 + lid) * A_STRIDE_H + lg * 8) = make_uint4(Pc[0], Pc[1], Pc[2], Pc[3]);
        *(uint4*)(myA + (3 * 32 + lid) * A_STRIDE_H + lg * 8) = make_uint4(Pd[0], Pd[1], Pd[2], Pd[3]);
    }
    __syncwarp();

    // Layer-1 B fragments (W0^T), per mma m16n8k16 spec; conflict-free.
    u32 Bf[2][8][2];
    #pragma unroll
    for (int kc = 0; kc < 2; kc++) {
        #pragma unroll
        for (int nt = 0; nt < 8; nt++) {
            const u32* wrow = (const u32*)&sW0h[(nt * 8 + g) * W_STRIDE_H + kc * 16];
            Bf[kc][nt][0] = wrow[tig];
            Bf[kc][nt][1] = wrow[tig + 4];
        }
    }
    // Layer-2 B fragments (m16n8k8), hi + lo split of W1.
    u32 Bf2h[8], Bf2l[8];
    #pragma unroll
    for (int nt = 0; nt < 8; nt++) {
        Bf2h[nt] = *(const u32*)&sW1h[g * 64 + nt * 8 + tig * 2];
        Bf2l[nt] = *(const u32*)&sW1l[g * 64 + nt * 8 + tig * 2];
    }

    // cw WITHOUT INV_FSCALE: hb stays in fp16-normal range, so the hi value
    // and its residual are both representable. 1/FSCALE folded into the
    // final output write.
    float cw[4];
    cw[0] = (1.0f - u) * (1.0f - v);
    cw[1] = u * (1.0f - v);
    cw[2] = (1.0f - u) * v;
    cw[3] = u * v;

    const int base = blockIdx.x * 128 + wid * 32;

    #pragma unroll
    for (int mtp = 0; mtp < 2; mtp++) {
        float hb[8][4];
        #pragma unroll
        for (int b = 0; b < 8; b++)
            #pragma unroll
            for (int c = 0; c < 4; c++) hb[b][c] = 0.0f;

        #pragma unroll
        for (int c = 0; c < 4; c++) {
            // D rows g / g+8 belong to points mtp*16+g / +8 -> fetch their
            // blend weights via shfl.
            float wlo = __shfl_sync(0xffffffffu, cw[c], mtp * 16 + g);
            float whi = __shfl_sync(0xffffffffu, cw[c], mtp * 16 + g + 8);

            u32 afr[2][4];
            #pragma unroll
            for (int kc = 0; kc < 2; kc++) {
                const __half* ar =
                    myA + (c * 32 + mtp * 16 + g) * A_STRIDE_H + kc * 16 + tig * 2;
                afr[kc][0] = *(const u32*)(ar);
                afr[kc][1] = *(const u32*)(ar + 8 * A_STRIDE_H);
                afr[kc][2] = *(const u32*)(ar + 8);
                afr[kc][3] = *(const u32*)(ar + 8 * A_STRIDE_H + 8);
            }
            #pragma unroll
            for (int nt = 0; nt < 8; nt++) {
                float d0 = 0.0f, d1 = 0.0f, d2 = 0.0f, d3 = 0.0f;
                asm volatile("mma.sync.aligned.m16n8k16.row.col.f32.f16.f16.f32 "
                    "{%0,%1,%2,%3},{%4,%5,%6,%7},{%8,%9},{%0,%1,%2,%3};"
                    : "+f"(d0), "+f"(d1), "+f"(d2), "+f"(d3)
                    : "r"(afr[0][0]), "r"(afr[0][1]), "r"(afr[0][2]), "r"(afr[0][3]),
                      "r"(Bf[0][nt][0]), "r"(Bf[0][nt][1]));
                asm volatile("mma.sync.aligned.m16n8k16.row.col.f32.f16.f16.f32 "
                    "{%0,%1,%2,%3},{%4,%5,%6,%7},{%8,%9},{%0,%1,%2,%3};"
                    : "+f"(d0), "+f"(d1), "+f"(d2), "+f"(d3)
                    : "r"(afr[1][0]), "r"(afr[1][1]), "r"(afr[1][2]), "r"(afr[1][3]),
                      "r"(Bf[1][nt][0]), "r"(Bf[1][nt][1]));
                hb[nt][0] = fmaf(fmaxf(d0, 0.0f), wlo, hb[nt][0]);
                hb[nt][1] = fmaf(fmaxf(d1, 0.0f), wlo, hb[nt][1]);
                hb[nt][2] = fmaf(fmaxf(d2, 0.0f), whi, hb[nt][2]);
                hb[nt][3] = fmaf(fmaxf(d3, 0.0f), whi, hb[nt][3]);
            }
        }

        // Layer 2 as MMA, 3-term split: h_hi*w_hi + h_lo*w_hi + h_hi*w_lo.
        float o0 = 0.0f, o1 = 0.0f, o2 = 0.0f, o3 = 0.0f;
        #pragma unroll
        for (int nt = 0; nt < 8; nt++) {
            __half2 h01 = __floats2half2_rn(hb[nt][0], hb[nt][1]);
            __half2 h23 = __floats2half2_rn(hb[nt][2], hb[nt][3]);
            float2 f01 = __half22float2(h01);
            float2 f23 = __half22float2(h23);
            u32 a0  = *reinterpret_cast<u32*>(&h01);
            u32 a1  = *reinterpret_cast<u32*>(&h23);
            u32 a0l = cvt_h2f(hb[nt][0] - f01.x, hb[nt][1] - f01.y);
            u32 a1l = cvt_h2f(hb[nt][2] - f23.x, hb[nt][3] - f23.y);
            asm volatile("mma.sync.aligned.m16n8k8.row.col.f32.f16.f16.f32 "
                "{%0,%1,%2,%3},{%4,%5},{%6},{%0,%1,%2,%3};"
                : "+f"(o0), "+f"(o1), "+f"(o2), "+f"(o3)
                : "r"(a0), "r"(a1), "r"(Bf2h[nt]));
            asm volatile("mma.sync.aligned.m16n8k8.row.col.f32.f16.f16.f32 "
                "{%0,%1,%2,%3},{%4,%5},{%6},{%0,%1,%2,%3};"
                : "+f"(o0), "+f"(o1), "+f"(o2), "+f"(o3)
                : "r"(a0l), "r"(a1l), "r"(Bf2h[nt]));
            asm volatile("mma.sync.aligned.m16n8k8.row.col.f32.f16.f16.f32 "
                "{%0,%1,%2,%3},{%4,%5},{%6},{%0,%1,%2,%3};"
                : "+f"(o0), "+f"(o1), "+f"(o2), "+f"(o3)
                : "r"(a0), "r"(a1), "r"(Bf2l[nt]));
        }
        o0 *= INV_FSCALE; o1 *= INV_FSCALE;
        o2 *= INV_FSCALE; o3 *= INV_FSCALE;

        int pt0 = base + mtp * 16 + g;
        if (pt0 < N)
            *(float2*)(out + (size_t)pt0 * 8 + 2 * tig) = make_float2(o0, o1);
        int pt1 = pt0 + 8;
        if (pt1 < N)
            *(float2*)(out + (size_t)pt1 * 8 + 2 * tig) = make_float2(o2, o3);
    }
}

extern "C" void kernel_launch(void* const* d_in, const int* in_sizes, int n_in,
                              void* d_out, int out_size)
{
    const float2* xy    = (const float2*)d_in[0];
    const float2* table = (const float2*)d_in[1];
    const float*  w0    = (const float*)d_in[2];
    const float*  w1    = (const float*)d_in[3];
    const unsigned* bound = (n_in > 4) ? (const unsigned*)d_in[4] : nullptr;
    int bound_elems = (n_in > 4) ? in_sizes[4] : 0;

    int N = in_sizes[0] / 2;

    // Level constants — same double-precision libm sequence as the numpy
    // reference so ceil() boundaries match exactly.
    Levels L;
    double b = exp2(log2(2048.0 / 16.0) / 15.0);
    unsigned off = 0;
    for (int l = 0; l < NLEV; l++) {
        double s = 16.0 * pow(b, (double)l) - 1.0;
        int r = (int)ceil(s) + 1;
        unsigned long long pp = (unsigned long long)r * (unsigned long long)r;
        unsigned psz = (pp > (unsigned long long)(1u << 19)) ? (1u << 19) : (unsigned)pp;
        psz = (psz + 7u) / 8u * 8u;
        L.scale[l]  = (float)s;
        L.res[l]    = (unsigned)r;
        L.size[l]   = psz;
        L.offset[l] = off;
        L.hashed[l] = (pp > (unsigned long long)psz) ? 1u : 0u;
        off += psz;
    }

    int blocks = (N + 127) / 128;
    plane_kernel<<<blocks, 128>>>(xy, table, w0, w1, bound, bound_elems,
                                  (float*)d_out, N, L);
}

// round 17
// speedup vs baseline: 1.6224x; 1.0153x over previous
#include <cuda_runtime.h>
#include <cuda_fp16.h>
#include <math.h>

#define NLEV 16
#define RESO 2048
#define PRIME_Y 2654435761u
#define FSCALE 4096.0f
#define INV_FSCALE (1.0f / 4096.0f)

#define A_STRIDE_H 40   // halves per A row: banks (20g+tig)%32 distinct -> conflict-free
#define W_STRIDE_H 40

struct Levels {
    float    scale[NLEV];
    unsigned res[NLEV];
    unsigned size[NLEV];
    unsigned offset[NLEV];
    unsigned hashed[NLEV];
};

typedef unsigned long long u64;
typedef unsigned int u32;

__device__ __forceinline__ u64 pk2(float lo, float hi) {
    u64 r; asm("mov.b64 %0,{%1,%2};" : "=l"(r) : "f"(lo), "f"(hi)); return r;
}
__device__ __forceinline__ float2 upk2(u64 a) {
    float2 f; asm("mov.b64 {%0,%1},%2;" : "=f"(f.x), "=f"(f.y) : "l"(a)); return f;
}
__device__ __forceinline__ u64 ffma2(u64 a, u64 b, u64 c) {
    u64 d; asm("fma.rn.f32x2 %0,%1,%2,%3;" : "=l"(d) : "l"(a), "l"(b), "l"(c)); return d;
}
__device__ __forceinline__ u64 mul2(u64 a, u64 b) {
    u64 d; asm("mul.rn.f32x2 %0,%1,%2;" : "=l"(d) : "l"(a), "l"(b)); return d;
}
__device__ __forceinline__ u32 cvt_h2(u64 pair) {
    float2 f = upk2(pair);
    __half2 hv = __floats2half2_rn(f.x, f.y);
    return *reinterpret_cast<u32*>(&hv);
}
__device__ __forceinline__ u32 cvt_h2f(float lo, float hi) {
    __half2 hv = __floats2half2_rn(lo, hi);
    return *reinterpret_cast<u32*>(&hv);
}

__device__ __forceinline__ float decode_bound(const unsigned* p, int elems) {
    if (!p || elems <= 0) return 1.0f;
    unsigned a = p[0];
    float ff = __uint_as_float(a);
    if (isfinite(ff) && fabsf(ff) > 1e-6f && fabsf(ff) < 1e9f) return ff;
    int ai = (int)a;
    if (ai != 0 && ai > -1000000000 && ai < 1000000000) return (float)ai;
    if (elems >= 2) {
        double d = __hiloint2double((int)p[1], (int)a);
        if (isfinite(d) && fabs(d) > 1e-6 && fabs(d) < 1e9) return (float)d;
    }
    return 1.0f;
}

__global__ __launch_bounds__(128, 4)
void plane_kernel(const float2* __restrict__ xy,
                  const float2* __restrict__ table,
                  const float*  __restrict__ w0g,
                  const float*  __restrict__ w1g,
                  const unsigned* __restrict__ bound_raw,
                  int bound_elems,
                  float* __restrict__ out,
                  int N, Levels L)
{
    __shared__ __align__(16) __half sA[4][128 * A_STRIDE_H];  // per-warp A staging
    __shared__ __align__(16) __half sW0h[64 * W_STRIDE_H];    // W0 fp16 [j][i]
    __shared__ __align__(16) __half sW1h[8 * 64];             // W1 hi fp16 [k][j]
    __shared__ __align__(16) __half sW1l[8 * 64];             // W1 lo fp16 (residual)

    const int tid = threadIdx.x;
    const int wid = tid >> 5;
    const int lid = tid & 31;
    const int g   = lid >> 2;   // groupID
    const int tig = lid & 3;    // threadID_in_group

    for (int i = tid; i < 64 * 32; i += 128) {
        int j = i >> 5, k = i & 31;
        sW0h[j * W_STRIDE_H + k] = __float2half(w0g[i]);
    }
    for (int i = tid; i < 8 * 64; i += 128) {
        float w = w1g[i];
        __half hi = __float2half(w);
        sW1h[i] = hi;
        sW1l[i] = __float2half(w - __half2float(hi));
    }
    __syncthreads();

    int n = blockIdx.x * 128 + tid;
    int nc = (n < N) ? n : (N - 1);

    float bound = decode_bound(bound_raw, bound_elems);

    float2 p = xy[nc];
    float inv2b = 0.5f / bound;
    float nxv = (p.x + bound) * inv2b;
    float nyv = (p.y + bound) * inv2b;
    float cxf = fminf(fmaxf(nxv * (float)RESO - 0.5f, 0.0f), (float)(RESO - 1));
    float cyf = fminf(fmaxf(nyv * (float)RESO - 0.5f, 0.0f), (float)(RESO - 1));
    float cx0 = floorf(cxf), cy0 = floorf(cyf);
    float cx1 = fminf(cx0 + 1.0f, (float)(RESO - 1));
    float cy1 = fminf(cy0 + 1.0f, (float)(RESO - 1));
    float u = cxf - cx0, v = cyf - cy0;

    float gx0 = (cx0 + 0.5f) * (1.0f / (float)RESO);
    float gx1 = (cx1 + 0.5f) * (1.0f / (float)RESO);
    float gyA = (cy0 + 0.5f) * (1.0f / (float)RESO);
    float gyB = (cy1 + 0.5f) * (1.0f / (float)RESO);

    __half* myA = sA[wid];

    // Encode in 4-level groups; stage each group's packed fp16 features.
    #pragma unroll
    for (int lg = 0; lg < 4; lg++) {
        u32 Pa[4], Pb[4], Pc[4], Pd[4];
        #pragma unroll
        for (int li = 0; li < 4; li++) {
            const int l = lg * 4 + li;
            float    scale  = L.scale[l];
            unsigned res    = L.res[l];
            unsigned size   = L.size[l];
            unsigned off    = L.offset[l];
            bool     hashed = (L.hashed[l] != 0);

            float pxa = fmaf(gx0, scale, 0.5f);
            float pxb = fmaf(gx1, scale, 0.5f);
            float pya = fmaf(gyA, scale, 0.5f);
            float pyb = fmaf(gyB, scale, 0.5f);
            float fxa = floorf(pxa), fxb = floorf(pxb);
            float fya = floorf(pya), fyb = floorf(pyb);
            float ua1 = pxa - fxa, ua0 = 1.0f - ua1;
            float ub1 = pxb - fxb, ub0 = 1.0f - ub1;
            float va1 = (pya - fya) * FSCALE, va0 = FSCALE - va1;
            float vb1 = (pyb - fyb) * FSCALE, vb0 = FSCALE - vb1;
            unsigned ix = (unsigned)fxa, iy = (unsigned)fya;
            bool bdx = fxb > fxa;
            bool bdy = fyb > fya;

            u64 T00, T01, T02, T10, T11, T12, T20, T21, T22;

            if (hashed) {
                // Hashed pair-merge: (x)^hy and (x^1)^hy differ only in bit0,
                // so they share one aligned 16B pair. With xA=ix&~1:
                //   pairA covers x in {xA, xA+1}, pairB covers {xA+2, xA+3}.
                // Loads/row = 1 + (odd(ix)||bdx), like the dense path.
                // Selection: t_r = (ix^hy_r)&1;
                //   T0 = t?A.y:A.x; T1 = t?(odd?B.x:A.x):(odd?B.y:A.y);
                //   T2 = t?B.y:B.x.  Bit-identical taps.
                unsigned m = size - 1u;
                unsigned hy0 = iy * PRIME_Y, hy1 = hy0 + PRIME_Y, hy2 = hy1 + PRIME_Y;
                bool odd = (ix & 1u);
                unsigned xA = ix & ~1u;
                unsigned pA0 = ((xA ^ hy0) & m) >> 1;
                unsigned pA1 = ((xA ^ hy1) & m) >> 1;
                unsigned pA2 = ((xA ^ hy2) & m) >> 1;
                unsigned pB0 = (((xA + 2u) ^ hy0) & m) >> 1;
                unsigned pB1 = (((xA + 2u) ^ hy1) & m) >> 1;
                unsigned pB2 = (((xA + 2u) ^ hy2) & m) >> 1;
                bool t0 = ((ix ^ hy0) & 1u);
                bool t1 = ((ix ^ hy1) & 1u);
                bool t2 = ((ix ^ hy2) & 1u);
                bool needB = odd || bdx;

                const ulonglong2* tb2 = (const ulonglong2*)(table + off);
                ulonglong2 A0 = __ldg(tb2 + pA0);
                ulonglong2 A1 = __ldg(tb2 + pA1);
                ulonglong2 B0 = make_ulonglong2(0ull, 0ull);
                ulonglong2 B1 = make_ulonglong2(0ull, 0ull);
                ulonglong2 A2 = make_ulonglong2(0ull, 0ull);
                ulonglong2 B2 = make_ulonglong2(0ull, 0ull);
                if (needB) { B0 = __ldg(tb2 + pB0); B1 = __ldg(tb2 + pB1); }
                if (bdy) {
                    A2 = __ldg(tb2 + pA2);
                    if (needB) B2 = __ldg(tb2 + pB2);
                }

                T00 = t0 ? A0.y : A0.x;
                T01 = t0 ? (odd ? B0.x : A0.x) : (odd ? B0.y : A0.y);
                T02 = t0 ? B0.y : B0.x;
                T10 = t1 ? A1.y : A1.x;
                T11 = t1 ? (odd ? B1.x : A1.x) : (odd ? B1.y : A1.y);
                T12 = t1 ? B1.y : B1.x;
                T20 = t2 ? A2.y : A2.x;
                T21 = t2 ? (odd ? B2.x : A2.x) : (odd ? B2.y : A2.y);
                T22 = t2 ? B2.y : B2.x;
            } else {
                // Dense pair-merge (R16): row taps are contiguous entries.
                unsigned hy0 = iy * res, hy1 = hy0 + res, hy2 = hy1 + res;
                unsigned b0 = ix + hy0; if (b0 >= size) b0 -= size;
                unsigned b1 = ix + hy1; if (b1 >= size) b1 -= size;
                unsigned b2 = ix + hy2; if (b2 >= size) b2 -= size;
                unsigned half = size >> 1;
                unsigned p00 = b0 >> 1, p01 = (p00 + 1u == half) ? 0u : p00 + 1u;
                unsigned p10 = b1 >> 1, p11 = (p10 + 1u == half) ? 0u : p10 + 1u;
                unsigned p20 = b2 >> 1, p21 = (p20 + 1u == half) ? 0u : p20 + 1u;
                bool od0 = (b0 & 1u), od1 = (b1 & 1u), od2 = (b2 & 1u);
                const ulonglong2* tb2 = (const ulonglong2*)(table + off);

                ulonglong2 A0 = __ldg(tb2 + p00);
                ulonglong2 B0 = __ldg(tb2 + p10);
                ulonglong2 A1 = make_ulonglong2(0ull, 0ull);
                ulonglong2 B1 = make_ulonglong2(0ull, 0ull);
                ulonglong2 C0 = make_ulonglong2(0ull, 0ull);
                ulonglong2 C1 = make_ulonglong2(0ull, 0ull);
                if (od0 || bdx) A1 = __ldg(tb2 + p01);
                if (od1 || bdx) B1 = __ldg(tb2 + p11);
                if (bdy) {
                    C0 = __ldg(tb2 + p20);
                    if (od2 || bdx) C1 = __ldg(tb2 + p21);
                }

                T00 = od0 ? A0.y : A0.x;
                T01 = od0 ? A1.x : A0.y;
                T02 = od0 ? A1.y : A1.x;
                T10 = od1 ? B0.y : B0.x;
                T11 = od1 ? B1.x : B0.y;
                T12 = od1 ? B1.y : B1.x;
                T20 = od2 ? C0.y : C0.x;
                T21 = od2 ? C1.x : C0.y;
                T22 = od2 ? C1.y : C1.x;
            }

            u64 ua0p = pk2(ua0, ua0), ua1p = pk2(ua1, ua1);
            u64 ub0p = pk2(ub0, ub0), ub1p = pk2(ub1, ub1);
            u64 va0p = pk2(va0, va0), va1p = pk2(va1, va1);
            u64 vb0p = pk2(vb0, vb0), vb1p = pk2(vb1, vb1);

            u64 S00 = ffma2(ua1p, T01, mul2(ua0p, T00));
            u64 S01 = ffma2(ua1p, T11, mul2(ua0p, T10));
            u64 S02 = ffma2(ua1p, T21, mul2(ua0p, T20));
            u64 X0r0 = bdx ? T01 : T00, X1r0 = bdx ? T02 : T01;
            u64 X0r1 = bdx ? T11 : T10, X1r1 = bdx ? T12 : T11;
            u64 X0r2 = bdx ? T21 : T20, X1r2 = bdx ? T22 : T21;
            u64 S10 = ffma2(ub1p, X1r0, mul2(ub0p, X0r0));
            u64 S11 = ffma2(ub1p, X1r1, mul2(ub0p, X0r1));
            u64 S12 = ffma2(ub1p, X1r2, mul2(ub0p, X0r2));

            Pa[li] = cvt_h2(ffma2(va1p, S01, mul2(va0p, S00)));
            Pb[li] = cvt_h2(ffma2(va1p, S11, mul2(va0p, S10)));
            u64 Y0a = bdy ? S01 : S00, Y1a = bdy ? S02 : S01;
            u64 Y0b = bdy ? S11 : S10, Y1b = bdy ? S12 : S11;
            Pc[li] = cvt_h2(ffma2(vb1p, Y1a, mul2(vb0p, Y0a)));
            Pd[li] = cvt_h2(ffma2(vb1p, Y1b, mul2(vb0p, Y0b)));
        }
        *(uint4*)(myA + (0 * 32 + lid) * A_STRIDE_H + lg * 8) = make_uint4(Pa[0], Pa[1], Pa[2], Pa[3]);
        *(uint4*)(myA + (1 * 32 + lid) * A_STRIDE_H + lg * 8) = make_uint4(Pb[0], Pb[1], Pb[2], Pb[3]);
        *(uint4*)(myA + (2 * 32 + lid) * A_STRIDE_H + lg * 8) = make_uint4(Pc[0], Pc[1], Pc[2], Pc[3]);
        *(uint4*)(myA + (3 * 32 + lid) * A_STRIDE_H + lg * 8) = make_uint4(Pd[0], Pd[1], Pd[2], Pd[3]);
    }
    __syncwarp();

    // Layer-1 B fragments (W0^T), per mma m16n8k16 spec; conflict-free.
    u32 Bf[2][8][2];
    #pragma unroll
    for (int kc = 0; kc < 2; kc++) {
        #pragma unroll
        for (int nt = 0; nt < 8; nt++) {
            const u32* wrow = (const u32*)&sW0h[(nt * 8 + g) * W_STRIDE_H + kc * 16];
            Bf[kc][nt][0] = wrow[tig];
            Bf[kc][nt][1] = wrow[tig + 4];
        }
    }
    // Layer-2 B fragments (m16n8k8), hi + lo split of W1.
    u32 Bf2h[8], Bf2l[8];
    #pragma unroll
    for (int nt = 0; nt < 8; nt++) {
        Bf2h[nt] = *(const u32*)&sW1h[g * 64 + nt * 8 + tig * 2];
        Bf2l[nt] = *(const u32*)&sW1l[g * 64 + nt * 8 + tig * 2];
    }

    // cw WITHOUT INV_FSCALE (keeps hb in fp16-normal range; 1/FSCALE folded
    // into the output write).
    float cw[4];
    cw[0] = (1.0f - u) * (1.0f - v);
    cw[1] = u * (1.0f - v);
    cw[2] = (1.0f - u) * v;
    cw[3] = u * v;

    const int base = blockIdx.x * 128 + wid * 32;

    #pragma unroll
    for (int mtp = 0; mtp < 2; mtp++) {
        float hb[8][4];
        #pragma unroll
        for (int b = 0; b < 8; b++)
            #pragma unroll
            for (int c = 0; c < 4; c++) hb[b][c] = 0.0f;

        #pragma unroll
        for (int c = 0; c < 4; c++) {
            // D rows g / g+8 belong to points mtp*16+g / +8 -> fetch their
            // blend weights via shfl.
            float wlo = __shfl_sync(0xffffffffu, cw[c], mtp * 16 + g);
            float whi = __shfl_sync(0xffffffffu, cw[c], mtp * 16 + g + 8);

            u32 afr[2][4];
            #pragma unroll
            for (int kc = 0; kc < 2; kc++) {
                const __half* ar =
                    myA + (c * 32 + mtp * 16 + g) * A_STRIDE_H + kc * 16 + tig * 2;
                afr[kc][0] = *(const u32*)(ar);
                afr[kc][1] = *(const u32*)(ar + 8 * A_STRIDE_H);
                afr[kc][2] = *(const u32*)(ar + 8);
                afr[kc][3] = *(const u32*)(ar + 8 * A_STRIDE_H + 8);
            }
            #pragma unroll
            for (int nt = 0; nt < 8; nt++) {
                float d0 = 0.0f, d1 = 0.0f, d2 = 0.0f, d3 = 0.0f;
                asm volatile("mma.sync.aligned.m16n8k16.row.col.f32.f16.f16.f32 "
                    "{%0,%1,%2,%3},{%4,%5,%6,%7},{%8,%9},{%0,%1,%2,%3};"
                    : "+f"(d0), "+f"(d1), "+f"(d2), "+f"(d3)
                    : "r"(afr[0][0]), "r"(afr[0][1]), "r"(afr[0][2]), "r"(afr[0][3]),
                      "r"(Bf[0][nt][0]), "r"(Bf[0][nt][1]));
                asm volatile("mma.sync.aligned.m16n8k16.row.col.f32.f16.f16.f32 "
                    "{%0,%1,%2,%3},{%4,%5,%6,%7},{%8,%9},{%0,%1,%2,%3};"
                    : "+f"(d0), "+f"(d1), "+f"(d2), "+f"(d3)
                    : "r"(afr[1][0]), "r"(afr[1][1]), "r"(afr[1][2]), "r"(afr[1][3]),
                      "r"(Bf[1][nt][0]), "r"(Bf[1][nt][1]));
                hb[nt][0] = fmaf(fmaxf(d0, 0.0f), wlo, hb[nt][0]);
                hb[nt][1] = fmaf(fmaxf(d1, 0.0f), wlo, hb[nt][1]);
                hb[nt][2] = fmaf(fmaxf(d2, 0.0f), whi, hb[nt][2]);
                hb[nt][3] = fmaf(fmaxf(d3, 0.0f), whi, hb[nt][3]);
            }
        }

        // Layer 2 as MMA, 3-term split: h_hi*w_hi + h_lo*w_hi + h_hi*w_lo.
        float o0 = 0.0f, o1 = 0.0f, o2 = 0.0f, o3 = 0.0f;
        #pragma unroll
        for (int nt = 0; nt < 8; nt++) {
            __half2 h01 = __floats2half2_rn(hb[nt][0], hb[nt][1]);
            __half2 h23 = __floats2half2_rn(hb[nt][2], hb[nt][3]);
            float2 f01 = __half22float2(h01);
            float2 f23 = __half22float2(h23);
            u32 a0  = *reinterpret_cast<u32*>(&h01);
            u32 a1  = *reinterpret_cast<u32*>(&h23);
            u32 a0l = cvt_h2f(hb[nt][0] - f01.x, hb[nt][1] - f01.y);
            u32 a1l = cvt_h2f(hb[nt][2] - f23.x, hb[nt][3] - f23.y);
            asm volatile("mma.sync.aligned.m16n8k8.row.col.f32.f16.f16.f32 "
                "{%0,%1,%2,%3},{%4,%5},{%6},{%0,%1,%2,%3};"
                : "+f"(o0), "+f"(o1), "+f"(o2), "+f"(o3)
                : "r"(a0), "r"(a1), "r"(Bf2h[nt]));
            asm volatile("mma.sync.aligned.m16n8k8.row.col.f32.f16.f16.f32 "
                "{%0,%1,%2,%3},{%4,%5},{%6},{%0,%1,%2,%3};"
                : "+f"(o0), "+f"(o1), "+f"(o2), "+f"(o3)
                : "r"(a0l), "r"(a1l), "r"(Bf2h[nt]));
            asm volatile("mma.sync.aligned.m16n8k8.row.col.f32.f16.f16.f32 "
                "{%0,%1,%2,%3},{%4,%5},{%6},{%0,%1,%2,%3};"
                : "+f"(o0), "+f"(o1), "+f"(o2), "+f"(o3)
                : "r"(a0), "r"(a1), "r"(Bf2l[nt]));
        }
        o0 *= INV_FSCALE; o1 *= INV_FSCALE;
        o2 *= INV_FSCALE; o3 *= INV_FSCALE;

        int pt0 = base + mtp * 16 + g;
        if (pt0 < N)
            *(float2*)(out + (size_t)pt0 * 8 + 2 * tig) = make_float2(o0, o1);
        int pt1 = pt0 + 8;
        if (pt1 < N)
            *(float2*)(out + (size_t)pt1 * 8 + 2 * tig) = make_float2(o2, o3);
    }
}

extern "C" void kernel_launch(void* const* d_in, const int* in_sizes, int n_in,
                              void* d_out, int out_size)
{
    const float2* xy    = (const float2*)d_in[0];
    const float2* table = (const float2*)d_in[1];
    const float*  w0    = (const float*)d_in[2];
    const float*  w1    = (const float*)d_in[3];
    const unsigned* bound = (n_in > 4) ? (const unsigned*)d_in[4] : nullptr;
    int bound_elems = (n_in > 4) ? in_sizes[4] : 0;

    int N = in_sizes[0] / 2;

    // Level constants — same double-precision libm sequence as the numpy
    // reference so ceil() boundaries match exactly.
    Levels L;
    double b = exp2(log2(2048.0 / 16.0) / 15.0);
    unsigned off = 0;
    for (int l = 0; l < NLEV; l++) {
        double s = 16.0 * pow(b, (double)l) - 1.0;
        int r = (int)ceil(s) + 1;
        unsigned long long pp = (unsigned long long)r * (unsigned long long)r;
        unsigned psz = (pp > (unsigned long long)(1u << 19)) ? (1u << 19) : (unsigned)pp;
        psz = (psz + 7u) / 8u * 8u;
        L.scale[l]  = (float)s;
        L.res[l]    = (unsigned)r;
        L.size[l]   = psz;
        L.offset[l] = off;
        L.hashed[l] = (pp > (unsigned long long)psz) ? 1u : 0u;
        off += psz;
    }

    int blocks = (N + 127) / 128;
    plane_kernel<<<blocks, 128>>>(xy, table, w0, w1, bound, bound_elems,
                                  (float*)d_out, N, L);
}